// round 10
// baseline (speedup 1.0000x reference)
#include <cuda_runtime.h>
#include <math.h>
#include <stdint.h>

#define M_ROWS 16384
#define K1 1024
#define N1 512
#define NANC 9
#define NBOX (M_ROWS*NANC)          /* 147456 */
#define PRE_NMS 6000
#define POST_NMS 300
#define IOU_THR 0.7f
#define REG_OFF (M_ROWS*NANC)            /* 147456 */
#define PROP_OFF (REG_OFF + M_ROWS*NANC*4) /* 737280 */
#define SEL_BLOCKS 288
#define NWORDS 188                      /* ceil(6000/32) */
#define EBUF_CAP 4096
#define INF_IDX 0x7FFFFFFF

// ---------------- scratch (device globals; no allocation) ----------------
__device__ float g_h[M_ROWS*N1];
__device__ float g_boxes[NBOX*4];
__device__ unsigned long long g_keys[NBOX];
__device__ unsigned long long g_ckeys[PRE_NMS];
__device__ unsigned long long g_ebuf[EBUF_CAP];
__device__ float g_sboxes[PRE_NMS*4];
__device__ unsigned int g_mask[PRE_NMS*NWORDS];
__device__ unsigned int g_hist[256];
__device__ unsigned long long g_prefix;
__device__ int g_krem;
__device__ int g_count;
__device__ int g_ecount;
__device__ unsigned int g_bar_count;
__device__ unsigned int g_epoch;
__device__ int g_dummy_sink;

// ================= helpers =================
__device__ __forceinline__ uint32_t smem_u32(const void* p) {
    uint32_t a;
    asm("{ .reg .u64 t; cvta.to.shared.u64 t, %1; cvt.u32.u64 %0, t; }" : "=r"(a) : "l"(p));
    return a;
}
__device__ __forceinline__ void split_tf32(float x, uint32_t& hi, uint32_t& lo) {
    hi = __float_as_uint(x) & 0xFFFFE000u;
    lo = __float_as_uint(x - __uint_as_float(hi));
}
__device__ __forceinline__ void mma_tf32(float* c, const uint32_t* a, uint32_t b0, uint32_t b1) {
    asm volatile(
        "mma.sync.aligned.m16n8k8.row.col.f32.tf32.tf32.f32 "
        "{%0,%1,%2,%3}, {%4,%5,%6,%7}, {%8,%9}, {%0,%1,%2,%3};"
        : "+f"(c[0]), "+f"(c[1]), "+f"(c[2]), "+f"(c[3])
        : "r"(a[0]), "r"(a[1]), "r"(a[2]), "r"(a[3]), "r"(b0), "r"(b1));
}
__device__ __forceinline__ void cp_async16(uint32_t dst, const void* src) {
    asm volatile("cp.async.ca.shared.global [%0], [%1], 16;" :: "r"(dst), "l"(src) : "memory");
}
__device__ __forceinline__ unsigned ld_cg_u32(const unsigned* p) {
    unsigned v;
    asm volatile("ld.global.cg.u32 %0, [%1];" : "=r"(v) : "l"(p) : "memory");
    return v;
}

// ---------------- dummy kernels (profiler slot steering) ----------------
__global__ void noop_a() { if (threadIdx.x == 1024) g_dummy_sink = 1; }
__global__ void noop_b() { if (threadIdx.x == 1024) g_dummy_sink = 2; }
__global__ void noop_c() { if (threadIdx.x == 1024) g_dummy_sink = 3; }

// ================= kernel 1: split-TF32 warp-MMA bottleneck GEMM =================
#define PADA 36
#define PADB 136
#define A_BUF_BYTES (128*PADA*4)
#define B_BUF_BYTES (32*PADB*4)
#define GEMM_SMEM (2*A_BUF_BYTES + 2*B_BUF_BYTES)

__global__ __launch_bounds__(256, 2)
void gemm_bneck_mma(const float* __restrict__ A, const float* __restrict__ W,
                    const float* __restrict__ bias) {
    extern __shared__ float sm[];
    float* As = sm;
    float* Bs = sm + 2*128*PADA;
    const uint32_t sA = smem_u32(As);
    const uint32_t sB = smem_u32(Bs);

    const int tid = threadIdx.x;
    const int lane = tid & 31;
    const int wid = tid >> 5;
    const int m0 = blockIdx.y * 128;
    const int n0 = blockIdx.x * 128;
    const int mrow = (wid & 3) * 32;
    const int ncol = (wid >> 2) * 64;
    const int quad = lane >> 2;
    const int tq = lane & 3;

    float c[2][8][4];
#pragma unroll
    for (int mt = 0; mt < 2; mt++)
#pragma unroll
        for (int nt = 0; nt < 8; nt++)
#pragma unroll
            for (int j = 0; j < 4; j++) c[mt][nt][j] = 0.f;

    auto prefetch = [&](int s, int buf) {
        const int k0 = s * 32;
#pragma unroll
        for (int i = 0; i < 4; i++) {
            int idx = tid + i * 256;
            int r = idx >> 3, c4 = idx & 7;
            cp_async16(sA + (uint32_t)buf * A_BUF_BYTES + (uint32_t)(r * PADA + c4 * 4) * 4,
                       A + (size_t)(m0 + r) * K1 + k0 + c4 * 4);
        }
#pragma unroll
        for (int i = 0; i < 4; i++) {
            int idx = tid + i * 256;
            int r = idx >> 5, c4 = idx & 31;
            cp_async16(sB + (uint32_t)buf * B_BUF_BYTES + (uint32_t)(r * PADB + c4 * 4) * 4,
                       W + (size_t)(k0 + r) * N1 + n0 + c4 * 4);
        }
        asm volatile("cp.async.commit_group;" ::: "memory");
    };

    prefetch(0, 0);

    for (int s = 0; s < 32; s++) {
        const int buf = s & 1;
        if (s < 31) {
            prefetch(s + 1, buf ^ 1);
            asm volatile("cp.async.wait_group 1;" ::: "memory");
        } else {
            asm volatile("cp.async.wait_group 0;" ::: "memory");
        }
        __syncthreads();

        const float* Ab = As + buf * (128 * PADA);
        const float* Bb = Bs + buf * (32 * PADB);

#pragma unroll
        for (int kk = 0; kk < 4; kk++) {
            uint32_t ah[2][4], al[2][4];
#pragma unroll
            for (int mt = 0; mt < 2; mt++) {
                const int rbase = mrow + mt * 16 + quad;
                const int cbase = kk * 8 + tq;
                float r0 = Ab[(rbase)     * PADA + cbase];
                float r1 = Ab[(rbase + 8) * PADA + cbase];
                float r2 = Ab[(rbase)     * PADA + cbase + 4];
                float r3 = Ab[(rbase + 8) * PADA + cbase + 4];
                split_tf32(r0, ah[mt][0], al[mt][0]);
                split_tf32(r1, ah[mt][1], al[mt][1]);
                split_tf32(r2, ah[mt][2], al[mt][2]);
                split_tf32(r3, ah[mt][3], al[mt][3]);
            }
#pragma unroll
            for (int nt = 0; nt < 8; nt++) {
                const int n = ncol + nt * 8 + quad;
                float b0r = Bb[(kk * 8 + tq)     * PADB + n];
                float b1r = Bb[(kk * 8 + tq + 4) * PADB + n];
                uint32_t bh0, bl0, bh1, bl1;
                split_tf32(b0r, bh0, bl0);
                split_tf32(b1r, bh1, bl1);
#pragma unroll
                for (int mt = 0; mt < 2; mt++) {
                    mma_tf32(c[mt][nt], ah[mt], bh0, bh1);
                    mma_tf32(c[mt][nt], ah[mt], bl0, bl1);
                    mma_tf32(c[mt][nt], al[mt], bh0, bh1);
                }
            }
        }
        __syncthreads();
    }

#pragma unroll
    for (int nt = 0; nt < 8; nt++) {
        const int nc = n0 + ncol + nt * 8 + 2 * tq;
        const float bia0 = __ldg(&bias[nc]);
        const float bia1 = __ldg(&bias[nc + 1]);
#pragma unroll
        for (int mt = 0; mt < 2; mt++) {
            const int row0 = m0 + mrow + mt * 16 + quad;
            float2 v01, v23;
            v01.x = fmaxf(c[mt][nt][0] + bia0, 0.f);
            v01.y = fmaxf(c[mt][nt][1] + bia1, 0.f);
            v23.x = fmaxf(c[mt][nt][2] + bia0, 0.f);
            v23.y = fmaxf(c[mt][nt][3] + bia1, 0.f);
            *(float2*)&g_h[(size_t)row0 * N1 + nc]       = v01;
            *(float2*)&g_h[(size_t)(row0 + 8) * N1 + nc] = v23;
        }
    }
}

// ---------------- kernel 2: head GEMM + sigmoid + box decode ----------------
__global__ __launch_bounds__(256, 4)
void head_kernel(const float* __restrict__ ancs,
                 const float* __restrict__ wc, const float* __restrict__ bc,
                 const float* __restrict__ wr, const float* __restrict__ br,
                 float* __restrict__ out) {
    __shared__ float Hs[32][64];
    __shared__ float Ws[32][48];
    __shared__ float Os[64][48];
    const int tid = threadIdx.x;
    const int tx = tid & 15;
    const int ty = tid >> 4;
    const int gr0 = blockIdx.x * 64;

    if (blockIdx.x == 0 && tid == 0) {
        g_prefix = 0ull;
        g_krem = PRE_NMS;
        g_count = 0;
        g_ecount = 0;
        g_bar_count = 0u;
        g_epoch = 0u;
    }

    float acc[4][3];
#pragma unroll
    for (int i = 0; i < 4; i++)
#pragma unroll
        for (int j = 0; j < 3; j++) acc[i][j] = 0.f;

    for (int k0 = 0; k0 < N1; k0 += 32) {
#pragma unroll
        for (int v = 0; v < 2; v++) {
            int lin = tid * 8 + v * 4;
            int r = lin >> 5;
            int c = lin & 31;
            float4 h4 = *(const float4*)&g_h[(size_t)(gr0 + r) * N1 + k0 + c];
            Hs[c + 0][r] = h4.x; Hs[c + 1][r] = h4.y;
            Hs[c + 2][r] = h4.z; Hs[c + 3][r] = h4.w;
        }
        for (int idx = tid; idx < 32 * 48; idx += 256) {
            int r = idx / 48, o = idx % 48;
            float v = 0.f;
            if (o < 9)       v = wc[(size_t)(k0 + r) * 9 + o];
            else if (o < 45) v = wr[(size_t)(k0 + r) * 36 + (o - 9)];
            Ws[r][o] = v;
        }
        __syncthreads();
#pragma unroll
        for (int k = 0; k < 32; k++) {
            float a0 = Hs[k][ty * 4 + 0], a1 = Hs[k][ty * 4 + 1];
            float a2 = Hs[k][ty * 4 + 2], a3 = Hs[k][ty * 4 + 3];
            float b0 = Ws[k][tx * 3 + 0], b1 = Ws[k][tx * 3 + 1], b2 = Ws[k][tx * 3 + 2];
            acc[0][0] += a0 * b0; acc[0][1] += a0 * b1; acc[0][2] += a0 * b2;
            acc[1][0] += a1 * b0; acc[1][1] += a1 * b1; acc[1][2] += a1 * b2;
            acc[2][0] += a2 * b0; acc[2][1] += a2 * b1; acc[2][2] += a2 * b2;
            acc[3][0] += a3 * b0; acc[3][1] += a3 * b1; acc[3][2] += a3 * b2;
        }
        __syncthreads();
    }
#pragma unroll
    for (int i = 0; i < 4; i++)
#pragma unroll
        for (int j = 0; j < 3; j++) {
            int o = tx * 3 + j;
            float bia = (o < 9) ? bc[o] : ((o < 45) ? br[o - 9] : 0.f);
            Os[ty * 4 + i][o] = acc[i][j] + bia;
        }
    __syncthreads();
    for (int idx = tid; idx < 64 * 45; idx += 256) {
        int r = idx / 45, o = idx % 45;
        float v = Os[r][o];
        int grow = gr0 + r;
        if (o < 9) out[(size_t)grow * 9 + o] = 1.f / (1.f + expf(-v));
        else       out[REG_OFF + (size_t)grow * 36 + (o - 9)] = v;
    }
    for (int t = tid; t < 64 * 9; t += 256) {
        int r = t / 9, a = t % 9;
        int gi = (gr0 + r) * 9 + a;
        float logit = Os[r][a];
        float score = 1.f / (1.f + expf(-logit));
        float tx_ = Os[r][9 + a * 4 + 0];
        float ty_ = Os[r][9 + a * 4 + 1];
        float tw_ = Os[r][9 + a * 4 + 2];
        float th_ = Os[r][9 + a * 4 + 3];
        float acx = ancs[(size_t)gi * 4 + 0];
        float acy = ancs[(size_t)gi * 4 + 1];
        float aw  = ancs[(size_t)gi * 4 + 2];
        float ah  = ancs[(size_t)gi * 4 + 3];
        float cx = acx + tx_ * aw;
        float cy = acy + ty_ * ah;
        float ww = aw * expf(tw_);
        float hh = ah * expf(th_);
        float x1 = fminf(fmaxf(cx - ww * 0.5f, 0.f), 1.f);
        float y1 = fminf(fmaxf(cy - hh * 0.5f, 0.f), 1.f);
        float x2 = fminf(fmaxf(cx + ww * 0.5f, 0.f), 1.f);
        float y2 = fminf(fmaxf(cy + hh * 0.5f, 0.f), 1.f);
        g_boxes[(size_t)gi * 4 + 0] = x1;
        g_boxes[(size_t)gi * 4 + 1] = y1;
        g_boxes[(size_t)gi * 4 + 2] = x2;
        g_boxes[(size_t)gi * 4 + 3] = y2;
        unsigned sb = __float_as_uint(score);
        g_keys[gi] = ((unsigned long long)sb << 32) | (unsigned long long)(~(unsigned)gi);
    }
}

// ===== selection: radix select on HIGH-32 bits (4 passes) + exact tie resolve =====
__global__ __launch_bounds__(256)
void select_all() {
    __shared__ unsigned int sh[256];
    __shared__ unsigned long long s_pref;
    __shared__ int s_last;
    const int tid = threadIdx.x;
    const int gs = gridDim.x * blockDim.x;
    const int gi = blockIdx.x * blockDim.x + tid;
    unsigned myep = 0;

    for (int p = 3; p >= 0; p--) {
        const int shift = 32 + p * 8;
        if (tid == 0)
            s_pref = (p == 3) ? 0ull : atomicAdd(&g_prefix, 0ull);
        sh[tid] = 0u;
        __syncthreads();
        const unsigned long long pref = s_pref;
        const unsigned long long mask = (p == 3) ? 0ull : (~0ull << (shift + 8));

        for (int i = gi; i < NBOX; i += gs) {
            unsigned long long k = g_keys[i];
            if (((k ^ pref) & mask) == 0ull)
                atomicAdd(&sh[(unsigned)(k >> shift) & 255u], 1u);
        }
        __syncthreads();
        if (sh[tid]) atomicAdd(&g_hist[tid], sh[tid]);
        __threadfence();
        myep++;

        if (tid == 0)
            s_last = (atomicAdd(&g_bar_count, 1u) == (unsigned)(gridDim.x - 1)) ? 1 : 0;
        __syncthreads();

        if (s_last) {
            sh[tid] = atomicAdd(&g_hist[tid], 0u);
            __syncthreads();
            if (tid == 0) {
                int k = atomicAdd(&g_krem, 0);
                int b = 255;
                for (; b >= 0; --b) {
                    int c = (int)sh[b];
                    if (c >= k) break;
                    k -= c;
                }
                if (b < 0) b = 0;
                atomicOr(&g_prefix, ((unsigned long long)(unsigned)b) << shift);
                atomicExch(&g_krem, k);
            }
            atomicExch(&g_hist[tid], 0u);
            __threadfence();
            __syncthreads();
            if (tid == 0) {
                atomicExch(&g_bar_count, 0u);
                __threadfence();
                atomicAdd(&g_epoch, 1u);
            }
        }
        if (tid == 0) {
            while (ld_cg_u32(&g_epoch) < myep) __nanosleep(64);
        }
        __syncthreads();
    }

    // compact: hi32 > thr_hi -> definite; hi32 == thr_hi -> side buffer
    if (tid == 0) s_pref = atomicAdd(&g_prefix, 0ull);
    __syncthreads();
    const unsigned thr_hi = (unsigned)(s_pref >> 32);
    for (int i = gi; i < NBOX; i += gs) {
        unsigned long long k = g_keys[i];
        const unsigned khi = (unsigned)(k >> 32);
        if (khi > thr_hi) {
            int pos = atomicAdd(&g_count, 1);
            if (pos < PRE_NMS) g_ckeys[pos] = k;
        } else if (khi == thr_hi) {
            int ep = atomicAdd(&g_ecount, 1);
            if (ep < EBUF_CAP) g_ebuf[ep] = k;
        }
    }
    __threadfence();
    if (tid == 0)
        s_last = (atomicAdd(&g_bar_count, 1u) == (unsigned)(gridDim.x - 1)) ? 1 : 0;
    __syncthreads();

    if (s_last) {
        // tie bucket: append top-r of the == thr_hi keys (exact; keys distinct)
        const int e = min(atomicAdd(&g_ecount, 0), EBUF_CAP);
        const int r = atomicAdd(&g_krem, 0);
        for (int j = tid; j < e; j += 256) {
            const unsigned long long kj = g_ebuf[j];
            int rank = 0;
            for (int l = 0; l < e; l++)
                rank += (g_ebuf[l] > kj) ? 1 : 0;
            if (rank < r) {
                int pos = atomicAdd(&g_count, 1);
                if (pos < PRE_NMS) g_ckeys[pos] = kj;
            }
        }
    }
}

// ===== NMS stage 1: parallel rank (keys distinct) + scatter boxes =====
#define RANK_ROWS 32
__global__ __launch_bounds__(256, 1)
void rank_kernel() {
    extern __shared__ unsigned long long skey[];
    __shared__ int scnt[RANK_ROWS];
    const int tid = threadIdx.x;
    const int nvalid = min(g_count, PRE_NMS);

    for (int i = tid; i < PRE_NMS; i += 256)
        skey[i] = (i < nvalid) ? g_ckeys[i] : 0ull;
    if (tid < RANK_ROWS) scnt[tid] = 0;
    __syncthreads();

    const int i0 = blockIdx.x * RANK_ROWS;
    const int e = tid >> 3;
    const int q = tid & 7;
    const int i = i0 + e;
    if (i < nvalid) {
        const unsigned long long ki = skey[i];
        const int j0 = q * (PRE_NMS / 8);
        const int j1 = (q == 7) ? PRE_NMS : j0 + (PRE_NMS / 8);
        int cnt = 0;
        for (int j = j0; j < j1; j++)
            cnt += (skey[j] > ki) ? 1 : 0;
        atomicAdd(&scnt[e], cnt);
    }
    __syncthreads();
    if (tid < RANK_ROWS) {
        const int ii = i0 + tid;
        if (ii < nvalid) {
            const int r = scnt[tid];
            const unsigned gidx = ~(unsigned)skey[ii];
            float4 b = *(const float4*)&g_boxes[(size_t)gidx * 4];
            *(float4*)&g_sboxes[(size_t)r * 4] = b;
        }
    }
}

// ===== NMS stage 2: pairwise IoU bitmask, warp-ballot, upper triangle =====
#define MASK_ROWS 32
__global__ __launch_bounds__(256, 1)
void mask_kernel() {
    extern __shared__ float4 sbox[];
    const int tid = threadIdx.x;
    const int lane = tid & 31;
    const int wrp = tid >> 5;
    for (int i = tid; i < PRE_NMS; i += 256)
        sbox[i] = *(const float4*)&g_sboxes[(size_t)i * 4];
    __syncthreads();

    const int i0 = blockIdx.x * MASK_ROWS;
    for (int p = wrp; p < MASK_ROWS * NWORDS; p += 8) {
        const int li = p / NWORDS;
        const int w = p % NWORDS;
        const int i = i0 + li;
        if (i >= PRE_NMS) break;
        if (w < (i >> 5)) continue;
        const int j = w * 32 + lane;
        bool sup = false;
        if (j < PRE_NMS) {
            const float4 bi = sbox[i];
            const float4 bj = sbox[j];
            const float ai = (bi.z - bi.x) * (bi.w - bi.y);
            const float aj = (bj.z - bj.x) * (bj.w - bj.y);
            float iw = fminf(bi.z, bj.z) - fmaxf(bi.x, bj.x);
            float ih = fminf(bi.w, bj.w) - fmaxf(bi.y, bj.y);
            iw = fmaxf(iw, 0.f);
            ih = fmaxf(ih, 0.f);
            const float inter = iw * ih;
            const float uni = ai + aj - inter;
            const float pthr = IOU_THR * uni;
            if (inter > pthr * 1.0001f)      sup = true;
            else if (inter < pthr * 0.9999f) sup = false;
            else {
                const float iou = (uni > 0.f) ? inter / uni : 0.f;
                sup = (iou > IOU_THR);
            }
        }
        const unsigned m = __ballot_sync(0xffffffffu, sup);
        if (lane == 0) g_mask[(size_t)i * NWORDS + w] = m;
    }
}

// ===== NMS stage 3: greedy scan, single warp, speculative next-winner =====
#define SCAN_WPL 6
__device__ __forceinline__ int warp_min_i(int v) {
#pragma unroll
    for (int off = 16; off > 0; off >>= 1)
        v = min(v, __shfl_xor_sync(0xffffffffu, v, off));
    return v;
}
__device__ __forceinline__ int first_alive(const unsigned rem[SCAN_WPL], int lane) {
    int cand = INF_IDX;
#pragma unroll
    for (int t = 0; t < SCAN_WPL; t++) {
        const unsigned u = ~rem[t];
        if (u != 0u && cand == INF_IDX)
            cand = (lane + 32 * t) * 32 + (__ffs(u) - 1);
    }
    return warp_min_i(cand);
}
// first two alive indices across the warp (exact)
__device__ __forceinline__ void first_two_alive(const unsigned rem[SCAN_WPL], int lane,
                                                int& c1, int& c2) {
    int f1 = INF_IDX, f2 = INF_IDX;
#pragma unroll
    for (int t = 0; t < SCAN_WPL; t++) {
        const unsigned u = ~rem[t];
        if (u != 0u) {
            const int base = (lane + 32 * t) * 32;
            if (f1 == INF_IDX) {
                f1 = base + (__ffs(u) - 1);
                const unsigned u2 = u & (u - 1u);
                if (u2 != 0u) f2 = base + (__ffs(u2) - 1);
            } else if (f2 == INF_IDX) {
                f2 = base + (__ffs(u) - 1);
            }
        }
    }
#pragma unroll
    for (int off = 16; off > 0; off >>= 1) {
        const int a2 = __shfl_xor_sync(0xffffffffu, f1, off);
        const int b2 = __shfl_xor_sync(0xffffffffu, f2, off);
        const int na = min(f1, a2);
        const int nb = min(max(f1, a2), min(f2, b2));
        f1 = na; f2 = nb;
    }
    c1 = f1; c2 = f2;
}
__device__ __forceinline__ void load_row(unsigned dst[SCAN_WPL], int r, int lane) {
    const unsigned* row = g_mask + (size_t)r * NWORDS;
#pragma unroll
    for (int t = 0; t < SCAN_WPL; t++) {
        const int w = lane + 32 * t;
        dst[t] = (w < NWORDS) ? row[w] : 0u;
    }
}
// OR winner's row (upper-triangle valid; fix the winner's own word)
__device__ __forceinline__ void apply_row(unsigned rem[SCAN_WPL],
                                          const unsigned roww[SCAN_WPL],
                                          int win, int lane) {
    const int ww = win >> 5;
#pragma unroll
    for (int t = 0; t < SCAN_WPL; t++) {
        const int w = lane + 32 * t;
        if (w < NWORDS && w >= ww) {
            unsigned m = roww[t];
            if (w == ww) {
                m |= (1u << (win & 31));
                m &= ~((1u << (win & 31)) - 1u);
            }
            rem[t] |= m;
        }
    }
}
// test bit idx of a distributed row; idx must be > the row's owner index
__device__ __forceinline__ int test_bit(const unsigned r[SCAN_WPL], int idx, int lane) {
    int mybit = 0;
    const int wq = idx >> 5;
#pragma unroll
    for (int t = 0; t < SCAN_WPL; t++)
        if (lane + 32 * t == wq) mybit = (int)((r[t] >> (idx & 31)) & 1u);
    return __ballot_sync(0xffffffffu, mybit != 0) != 0u;
}

__global__ __launch_bounds__(32, 1)
void scan_kernel(float* __restrict__ out) {
    const int lane = threadIdx.x;
    const int nvalid = min(g_count, PRE_NMS);

    unsigned rem[SCAN_WPL];
#pragma unroll
    for (int t = 0; t < SCAN_WPL; t++) {
        const int w = lane + 32 * t;
        unsigned v = 0xFFFFFFFFu;
        if (w < NWORDS) {
            v = 0u;
            const int base = w * 32;
            if (base + 32 > nvalid) {
                for (int b = 0; b < 32; b++)
                    if (base + b >= nvalid) v |= (1u << b);
            }
        }
        rem[t] = v;
    }

    int w = first_alive(rem, lane);
    unsigned roww[SCAN_WPL];
    if (w != INF_IDX) load_row(roww, w, lane);

    int it = 0;
    while (it < POST_NMS && w != INF_IDX) {
        if (lane < 4)
            out[PROP_OFF + it * 4 + lane] = g_sboxes[(size_t)w * 4 + lane];
        it++;

        // remove winner from alive set (so candidates exclude it)
        {
            const int wq = w >> 5;
#pragma unroll
            for (int t = 0; t < SCAN_WPL; t++)
                if (lane + 32 * t == wq) rem[t] |= (1u << (w & 31));
        }
        // candidates BEFORE suppression OR
        int c1, c2;
        first_two_alive(rem, lane, c1, c2);

        // speculative row loads (independent of roww consumption)
        unsigned r1[SCAN_WPL], r2[SCAN_WPL];
        if (c1 != INF_IDX) load_row(r1, c1, lane);
        if (c2 != INF_IDX) load_row(r2, c2, lane);

        // apply winner's suppression row
        apply_row(rem, roww, w, lane);

        // choose next winner (c1/c2 > w, so their bits in roww are valid)
        if (c1 == INF_IDX) {
            w = INF_IDX;
        } else if (!test_bit(roww, c1, lane)) {
            w = c1;
#pragma unroll
            for (int t = 0; t < SCAN_WPL; t++) roww[t] = r1[t];
        } else if (c2 != INF_IDX && !test_bit(roww, c2, lane)) {
            w = c2;
#pragma unroll
            for (int t = 0; t < SCAN_WPL; t++) roww[t] = r2[t];
        } else {
            w = first_alive(rem, lane);   // exact slow path
            if (w != INF_IDX) load_row(roww, w, lane);
        }
    }
    for (int idx = it * 4 + lane; idx < POST_NMS * 4; idx += 32)
        out[PROP_OFF + idx] = 0.f;
}

// ---------------- launcher ----------------
extern "C" void kernel_launch(void* const* d_in, const int* in_sizes, int n_in,
                              void* d_out, int out_size) {
    const float* feats   = (const float*)d_in[0];
    const float* ancs    = (const float*)d_in[1];
    const float* w_bneck = (const float*)d_in[3];
    const float* b_bneck = (const float*)d_in[4];
    const float* w_cls   = (const float*)d_in[5];
    const float* b_cls   = (const float*)d_in[6];
    const float* w_reg   = (const float*)d_in[7];
    const float* b_reg   = (const float*)d_in[8];
    float* out = (float*)d_out;

    cudaFuncSetAttribute(gemm_bneck_mma, cudaFuncAttributeMaxDynamicSharedMemorySize, GEMM_SMEM);
    cudaFuncSetAttribute(rank_kernel, cudaFuncAttributeMaxDynamicSharedMemorySize, PRE_NMS * 8);
    cudaFuncSetAttribute(mask_kernel, cudaFuncAttributeMaxDynamicSharedMemorySize, PRE_NMS * 16);

    // profiler slot steering: ncu captures the 4th launch -> gemm
    noop_a<<<1, 32>>>();
    noop_b<<<1, 32>>>();
    noop_c<<<1, 32>>>();

    gemm_bneck_mma<<<dim3(4, 128), 256, GEMM_SMEM>>>(feats, w_bneck, b_bneck);
    head_kernel<<<M_ROWS / 64, 256>>>(ancs, w_cls, b_cls, w_reg, b_reg, out);
    select_all<<<SEL_BLOCKS, 256>>>();
    rank_kernel<<<(PRE_NMS + RANK_ROWS - 1) / RANK_ROWS, 256, PRE_NMS * 8>>>();
    mask_kernel<<<(PRE_NMS + MASK_ROWS - 1) / MASK_ROWS, 256, PRE_NMS * 16>>>();
    scan_kernel<<<1, 32>>>(out);
}

// round 11
// speedup vs baseline: 1.1301x; 1.1301x over previous
#include <cuda_runtime.h>
#include <math.h>
#include <stdint.h>

#define M_ROWS 16384
#define K1 1024
#define N1 512
#define NANC 9
#define NBOX (M_ROWS*NANC)          /* 147456 */
#define PRE_NMS 6000
#define POST_NMS 300
#define IOU_THR 0.7f
#define REG_OFF (M_ROWS*NANC)            /* 147456 */
#define PROP_OFF (REG_OFF + M_ROWS*NANC*4) /* 737280 */
#define SEL_BLOCKS 288
#define NWORDS 188                      /* ceil(6000/32) */
#define EBUF_CAP 4096

// ---------------- scratch (device globals; no allocation) ----------------
__device__ float g_h[M_ROWS*N1];
__device__ float g_boxes[NBOX*4];
__device__ unsigned long long g_keys[NBOX];
__device__ unsigned long long g_ckeys[PRE_NMS];
__device__ unsigned long long g_ebuf[EBUF_CAP];
__device__ float g_sboxes[PRE_NMS*4];
__device__ unsigned int g_mask[PRE_NMS*NWORDS];
__device__ unsigned int g_hist[256];
__device__ unsigned long long g_prefix;
__device__ int g_krem;
__device__ int g_count;
__device__ int g_ecount;
__device__ unsigned int g_bar_count;
__device__ unsigned int g_epoch;
__device__ int g_dummy_sink;

// ================= helpers =================
__device__ __forceinline__ uint32_t smem_u32(const void* p) {
    uint32_t a;
    asm("{ .reg .u64 t; cvta.to.shared.u64 t, %1; cvt.u32.u64 %0, t; }" : "=r"(a) : "l"(p));
    return a;
}
__device__ __forceinline__ void split_tf32(float x, uint32_t& hi, uint32_t& lo) {
    hi = __float_as_uint(x) & 0xFFFFE000u;
    lo = __float_as_uint(x - __uint_as_float(hi));
}
__device__ __forceinline__ void mma_tf32(float* c, const uint32_t* a, uint32_t b0, uint32_t b1) {
    asm volatile(
        "mma.sync.aligned.m16n8k8.row.col.f32.tf32.tf32.f32 "
        "{%0,%1,%2,%3}, {%4,%5,%6,%7}, {%8,%9}, {%0,%1,%2,%3};"
        : "+f"(c[0]), "+f"(c[1]), "+f"(c[2]), "+f"(c[3])
        : "r"(a[0]), "r"(a[1]), "r"(a[2]), "r"(a[3]), "r"(b0), "r"(b1));
}
__device__ __forceinline__ void cp_async16(uint32_t dst, const void* src) {
    asm volatile("cp.async.ca.shared.global [%0], [%1], 16;" :: "r"(dst), "l"(src) : "memory");
}
__device__ __forceinline__ unsigned ld_cg_u32(const unsigned* p) {
    unsigned v;
    asm volatile("ld.global.cg.u32 %0, [%1];" : "=r"(v) : "l"(p) : "memory");
    return v;
}

// ---------------- dummy kernel (profiler slot steering) ----------------
__global__ void noop_a() { if (threadIdx.x == 1024) g_dummy_sink = 1; }

// ================= kernel 1: split-TF32 warp-MMA bottleneck GEMM =================
#define PADA 36
#define PADB 136
#define A_BUF_BYTES (128*PADA*4)
#define B_BUF_BYTES (32*PADB*4)
#define GEMM_SMEM (2*A_BUF_BYTES + 2*B_BUF_BYTES)

__global__ __launch_bounds__(256, 2)
void gemm_bneck_mma(const float* __restrict__ A, const float* __restrict__ W,
                    const float* __restrict__ bias) {
    extern __shared__ float sm[];
    float* As = sm;
    float* Bs = sm + 2*128*PADA;
    const uint32_t sA = smem_u32(As);
    const uint32_t sB = smem_u32(Bs);

    const int tid = threadIdx.x;
    const int lane = tid & 31;
    const int wid = tid >> 5;
    const int m0 = blockIdx.y * 128;
    const int n0 = blockIdx.x * 128;
    const int mrow = (wid & 3) * 32;
    const int ncol = (wid >> 2) * 64;
    const int quad = lane >> 2;
    const int tq = lane & 3;

    float c[2][8][4];
#pragma unroll
    for (int mt = 0; mt < 2; mt++)
#pragma unroll
        for (int nt = 0; nt < 8; nt++)
#pragma unroll
            for (int j = 0; j < 4; j++) c[mt][nt][j] = 0.f;

    auto prefetch = [&](int s, int buf) {
        const int k0 = s * 32;
#pragma unroll
        for (int i = 0; i < 4; i++) {
            int idx = tid + i * 256;
            int r = idx >> 3, c4 = idx & 7;
            cp_async16(sA + (uint32_t)buf * A_BUF_BYTES + (uint32_t)(r * PADA + c4 * 4) * 4,
                       A + (size_t)(m0 + r) * K1 + k0 + c4 * 4);
        }
#pragma unroll
        for (int i = 0; i < 4; i++) {
            int idx = tid + i * 256;
            int r = idx >> 5, c4 = idx & 31;
            cp_async16(sB + (uint32_t)buf * B_BUF_BYTES + (uint32_t)(r * PADB + c4 * 4) * 4,
                       W + (size_t)(k0 + r) * N1 + n0 + c4 * 4);
        }
        asm volatile("cp.async.commit_group;" ::: "memory");
    };

    prefetch(0, 0);

    for (int s = 0; s < 32; s++) {
        const int buf = s & 1;
        if (s < 31) {
            prefetch(s + 1, buf ^ 1);
            asm volatile("cp.async.wait_group 1;" ::: "memory");
        } else {
            asm volatile("cp.async.wait_group 0;" ::: "memory");
        }
        __syncthreads();

        const float* Ab = As + buf * (128 * PADA);
        const float* Bb = Bs + buf * (32 * PADB);

#pragma unroll
        for (int kk = 0; kk < 4; kk++) {
            uint32_t ah[2][4], al[2][4];
#pragma unroll
            for (int mt = 0; mt < 2; mt++) {
                const int rbase = mrow + mt * 16 + quad;
                const int cbase = kk * 8 + tq;
                float r0 = Ab[(rbase)     * PADA + cbase];
                float r1 = Ab[(rbase + 8) * PADA + cbase];
                float r2 = Ab[(rbase)     * PADA + cbase + 4];
                float r3 = Ab[(rbase + 8) * PADA + cbase + 4];
                split_tf32(r0, ah[mt][0], al[mt][0]);
                split_tf32(r1, ah[mt][1], al[mt][1]);
                split_tf32(r2, ah[mt][2], al[mt][2]);
                split_tf32(r3, ah[mt][3], al[mt][3]);
            }
#pragma unroll
            for (int nt = 0; nt < 8; nt++) {
                const int n = ncol + nt * 8 + quad;
                float b0r = Bb[(kk * 8 + tq)     * PADB + n];
                float b1r = Bb[(kk * 8 + tq + 4) * PADB + n];
                uint32_t bh0, bl0, bh1, bl1;
                split_tf32(b0r, bh0, bl0);
                split_tf32(b1r, bh1, bl1);
#pragma unroll
                for (int mt = 0; mt < 2; mt++) {
                    mma_tf32(c[mt][nt], ah[mt], bh0, bh1);
                    mma_tf32(c[mt][nt], ah[mt], bl0, bl1);
                    mma_tf32(c[mt][nt], al[mt], bh0, bh1);
                }
            }
        }
        __syncthreads();
    }

#pragma unroll
    for (int nt = 0; nt < 8; nt++) {
        const int nc = n0 + ncol + nt * 8 + 2 * tq;
        const float bia0 = __ldg(&bias[nc]);
        const float bia1 = __ldg(&bias[nc + 1]);
#pragma unroll
        for (int mt = 0; mt < 2; mt++) {
            const int row0 = m0 + mrow + mt * 16 + quad;
            float2 v01, v23;
            v01.x = fmaxf(c[mt][nt][0] + bia0, 0.f);
            v01.y = fmaxf(c[mt][nt][1] + bia1, 0.f);
            v23.x = fmaxf(c[mt][nt][2] + bia0, 0.f);
            v23.y = fmaxf(c[mt][nt][3] + bia1, 0.f);
            *(float2*)&g_h[(size_t)row0 * N1 + nc]       = v01;
            *(float2*)&g_h[(size_t)(row0 + 8) * N1 + nc] = v23;
        }
    }
}

// ---------------- kernel 2: head GEMM + sigmoid + box decode ----------------
__global__ __launch_bounds__(256, 4)
void head_kernel(const float* __restrict__ ancs,
                 const float* __restrict__ wc, const float* __restrict__ bc,
                 const float* __restrict__ wr, const float* __restrict__ br,
                 float* __restrict__ out) {
    __shared__ float Hs[32][64];
    __shared__ float Ws[32][48];
    __shared__ float Os[64][48];
    const int tid = threadIdx.x;
    const int tx = tid & 15;
    const int ty = tid >> 4;
    const int gr0 = blockIdx.x * 64;

    if (blockIdx.x == 0 && tid == 0) {
        g_prefix = 0ull;
        g_krem = PRE_NMS;
        g_count = 0;
        g_ecount = 0;
        g_bar_count = 0u;
        g_epoch = 0u;
    }

    float acc[4][3];
#pragma unroll
    for (int i = 0; i < 4; i++)
#pragma unroll
        for (int j = 0; j < 3; j++) acc[i][j] = 0.f;

    for (int k0 = 0; k0 < N1; k0 += 32) {
#pragma unroll
        for (int v = 0; v < 2; v++) {
            int lin = tid * 8 + v * 4;
            int r = lin >> 5;
            int c = lin & 31;
            float4 h4 = *(const float4*)&g_h[(size_t)(gr0 + r) * N1 + k0 + c];
            Hs[c + 0][r] = h4.x; Hs[c + 1][r] = h4.y;
            Hs[c + 2][r] = h4.z; Hs[c + 3][r] = h4.w;
        }
        for (int idx = tid; idx < 32 * 48; idx += 256) {
            int r = idx / 48, o = idx % 48;
            float v = 0.f;
            if (o < 9)       v = wc[(size_t)(k0 + r) * 9 + o];
            else if (o < 45) v = wr[(size_t)(k0 + r) * 36 + (o - 9)];
            Ws[r][o] = v;
        }
        __syncthreads();
#pragma unroll
        for (int k = 0; k < 32; k++) {
            float a0 = Hs[k][ty * 4 + 0], a1 = Hs[k][ty * 4 + 1];
            float a2 = Hs[k][ty * 4 + 2], a3 = Hs[k][ty * 4 + 3];
            float b0 = Ws[k][tx * 3 + 0], b1 = Ws[k][tx * 3 + 1], b2 = Ws[k][tx * 3 + 2];
            acc[0][0] += a0 * b0; acc[0][1] += a0 * b1; acc[0][2] += a0 * b2;
            acc[1][0] += a1 * b0; acc[1][1] += a1 * b1; acc[1][2] += a1 * b2;
            acc[2][0] += a2 * b0; acc[2][1] += a2 * b1; acc[2][2] += a2 * b2;
            acc[3][0] += a3 * b0; acc[3][1] += a3 * b1; acc[3][2] += a3 * b2;
        }
        __syncthreads();
    }
#pragma unroll
    for (int i = 0; i < 4; i++)
#pragma unroll
        for (int j = 0; j < 3; j++) {
            int o = tx * 3 + j;
            float bia = (o < 9) ? bc[o] : ((o < 45) ? br[o - 9] : 0.f);
            Os[ty * 4 + i][o] = acc[i][j] + bia;
        }
    __syncthreads();
    for (int idx = tid; idx < 64 * 45; idx += 256) {
        int r = idx / 45, o = idx % 45;
        float v = Os[r][o];
        int grow = gr0 + r;
        if (o < 9) out[(size_t)grow * 9 + o] = 1.f / (1.f + expf(-v));
        else       out[REG_OFF + (size_t)grow * 36 + (o - 9)] = v;
    }
    for (int t = tid; t < 64 * 9; t += 256) {
        int r = t / 9, a = t % 9;
        int gi = (gr0 + r) * 9 + a;
        float logit = Os[r][a];
        float score = 1.f / (1.f + expf(-logit));
        float tx_ = Os[r][9 + a * 4 + 0];
        float ty_ = Os[r][9 + a * 4 + 1];
        float tw_ = Os[r][9 + a * 4 + 2];
        float th_ = Os[r][9 + a * 4 + 3];
        float acx = ancs[(size_t)gi * 4 + 0];
        float acy = ancs[(size_t)gi * 4 + 1];
        float aw  = ancs[(size_t)gi * 4 + 2];
        float ah  = ancs[(size_t)gi * 4 + 3];
        float cx = acx + tx_ * aw;
        float cy = acy + ty_ * ah;
        float ww = aw * expf(tw_);
        float hh = ah * expf(th_);
        float x1 = fminf(fmaxf(cx - ww * 0.5f, 0.f), 1.f);
        float y1 = fminf(fmaxf(cy - hh * 0.5f, 0.f), 1.f);
        float x2 = fminf(fmaxf(cx + ww * 0.5f, 0.f), 1.f);
        float y2 = fminf(fmaxf(cy + hh * 0.5f, 0.f), 1.f);
        g_boxes[(size_t)gi * 4 + 0] = x1;
        g_boxes[(size_t)gi * 4 + 1] = y1;
        g_boxes[(size_t)gi * 4 + 2] = x2;
        g_boxes[(size_t)gi * 4 + 3] = y2;
        unsigned sb = __float_as_uint(score);
        g_keys[gi] = ((unsigned long long)sb << 32) | (unsigned long long)(~(unsigned)gi);
    }
}

// ===== selection: radix select on HIGH-32 bits (4 passes) + exact tie resolve =====
__global__ __launch_bounds__(256)
void select_all() {
    __shared__ unsigned int sh[256];
    __shared__ unsigned long long s_pref;
    __shared__ int s_last;
    const int tid = threadIdx.x;
    const int gs = gridDim.x * blockDim.x;
    const int gi = blockIdx.x * blockDim.x + tid;
    unsigned myep = 0;

    for (int p = 3; p >= 0; p--) {
        const int shift = 32 + p * 8;
        if (tid == 0)
            s_pref = (p == 3) ? 0ull : atomicAdd(&g_prefix, 0ull);
        sh[tid] = 0u;
        __syncthreads();
        const unsigned long long pref = s_pref;
        const unsigned long long mask = (p == 3) ? 0ull : (~0ull << (shift + 8));

        for (int i = gi; i < NBOX; i += gs) {
            unsigned long long k = g_keys[i];
            if (((k ^ pref) & mask) == 0ull)
                atomicAdd(&sh[(unsigned)(k >> shift) & 255u], 1u);
        }
        __syncthreads();
        if (sh[tid]) atomicAdd(&g_hist[tid], sh[tid]);
        __threadfence();
        myep++;

        if (tid == 0)
            s_last = (atomicAdd(&g_bar_count, 1u) == (unsigned)(gridDim.x - 1)) ? 1 : 0;
        __syncthreads();

        if (s_last) {
            sh[tid] = atomicAdd(&g_hist[tid], 0u);
            __syncthreads();
            if (tid == 0) {
                int k = atomicAdd(&g_krem, 0);
                int b = 255;
                for (; b >= 0; --b) {
                    int c = (int)sh[b];
                    if (c >= k) break;
                    k -= c;
                }
                if (b < 0) b = 0;
                atomicOr(&g_prefix, ((unsigned long long)(unsigned)b) << shift);
                atomicExch(&g_krem, k);
            }
            atomicExch(&g_hist[tid], 0u);
            __threadfence();
            __syncthreads();
            if (tid == 0) {
                atomicExch(&g_bar_count, 0u);
                __threadfence();
                atomicAdd(&g_epoch, 1u);
            }
        }
        if (tid == 0) {
            while (ld_cg_u32(&g_epoch) < myep) __nanosleep(64);
        }
        __syncthreads();
    }

    // compact: hi32 > thr_hi -> definite; hi32 == thr_hi -> side buffer
    if (tid == 0) s_pref = atomicAdd(&g_prefix, 0ull);
    __syncthreads();
    const unsigned thr_hi = (unsigned)(s_pref >> 32);
    for (int i = gi; i < NBOX; i += gs) {
        unsigned long long k = g_keys[i];
        const unsigned khi = (unsigned)(k >> 32);
        if (khi > thr_hi) {
            int pos = atomicAdd(&g_count, 1);
            if (pos < PRE_NMS) g_ckeys[pos] = k;
        } else if (khi == thr_hi) {
            int ep = atomicAdd(&g_ecount, 1);
            if (ep < EBUF_CAP) g_ebuf[ep] = k;
        }
    }
    __threadfence();
    if (tid == 0)
        s_last = (atomicAdd(&g_bar_count, 1u) == (unsigned)(gridDim.x - 1)) ? 1 : 0;
    __syncthreads();

    if (s_last) {
        const int e = min(atomicAdd(&g_ecount, 0), EBUF_CAP);
        const int r = atomicAdd(&g_krem, 0);
        for (int j = tid; j < e; j += 256) {
            const unsigned long long kj = g_ebuf[j];
            int rank = 0;
            for (int l = 0; l < e; l++)
                rank += (g_ebuf[l] > kj) ? 1 : 0;
            if (rank < r) {
                int pos = atomicAdd(&g_count, 1);
                if (pos < PRE_NMS) g_ckeys[pos] = kj;
            }
        }
    }
}

// ===== NMS stage 1: parallel rank (keys distinct) + scatter boxes =====
#define RANK_ROWS 32
__global__ __launch_bounds__(256, 1)
void rank_kernel() {
    extern __shared__ unsigned long long skey[];
    __shared__ int scnt[RANK_ROWS];
    const int tid = threadIdx.x;
    const int nvalid = min(g_count, PRE_NMS);

    for (int i = tid; i < PRE_NMS; i += 256)
        skey[i] = (i < nvalid) ? g_ckeys[i] : 0ull;
    if (tid < RANK_ROWS) scnt[tid] = 0;
    __syncthreads();

    const int i0 = blockIdx.x * RANK_ROWS;
    const int e = tid >> 3;
    const int q = tid & 7;
    const int i = i0 + e;
    if (i < nvalid) {
        const unsigned long long ki = skey[i];
        const int j0 = q * (PRE_NMS / 8);
        const int j1 = (q == 7) ? PRE_NMS : j0 + (PRE_NMS / 8);
        int cnt = 0;
        for (int j = j0; j < j1; j++)
            cnt += (skey[j] > ki) ? 1 : 0;
        atomicAdd(&scnt[e], cnt);
    }
    __syncthreads();
    if (tid < RANK_ROWS) {
        const int ii = i0 + tid;
        if (ii < nvalid) {
            const int r = scnt[tid];
            const unsigned gidx = ~(unsigned)skey[ii];
            float4 b = *(const float4*)&g_boxes[(size_t)gidx * 4];
            *(float4*)&g_sboxes[(size_t)r * 4] = b;
        }
    }
}

// ===== NMS stage 2: pairwise IoU bitmask, warp-ballot, upper triangle =====
#define MASK_ROWS 32
__global__ __launch_bounds__(256, 1)
void mask_kernel() {
    extern __shared__ float4 sbox[];
    const int tid = threadIdx.x;
    const int lane = tid & 31;
    const int wrp = tid >> 5;
    for (int i = tid; i < PRE_NMS; i += 256)
        sbox[i] = *(const float4*)&g_sboxes[(size_t)i * 4];
    __syncthreads();

    const int i0 = blockIdx.x * MASK_ROWS;
    for (int p = wrp; p < MASK_ROWS * NWORDS; p += 8) {
        const int li = p / NWORDS;
        const int w = p % NWORDS;
        const int i = i0 + li;
        if (i >= PRE_NMS) break;
        if (w < (i >> 5)) continue;
        const int j = w * 32 + lane;
        bool sup = false;
        if (j < PRE_NMS) {
            const float4 bi = sbox[i];
            const float4 bj = sbox[j];
            const float ai = (bi.z - bi.x) * (bi.w - bi.y);
            const float aj = (bj.z - bj.x) * (bj.w - bj.y);
            float iw = fminf(bi.z, bj.z) - fmaxf(bi.x, bj.x);
            float ih = fminf(bi.w, bj.w) - fmaxf(bi.y, bj.y);
            iw = fmaxf(iw, 0.f);
            ih = fmaxf(ih, 0.f);
            const float inter = iw * ih;
            const float uni = ai + aj - inter;
            const float pthr = IOU_THR * uni;
            if (inter > pthr * 1.0001f)      sup = true;
            else if (inter < pthr * 0.9999f) sup = false;
            else {
                const float iou = (uni > 0.f) ? inter / uni : 0.f;
                sup = (iou > IOU_THR);
            }
        }
        const unsigned m = __ballot_sync(0xffffffffu, sup);
        if (lane == 0) g_mask[(size_t)i * NWORDS + w] = m;
    }
}

// ===== NMS stage 3: greedy scan, single warp, bitmap in registers (R9 version) =====
#define SCAN_WPL 6
__global__ __launch_bounds__(32, 1)
void scan_kernel(float* __restrict__ out) {
    const int lane = threadIdx.x;
    const int nvalid = min(g_count, PRE_NMS);

    unsigned rem[SCAN_WPL];
#pragma unroll
    for (int t = 0; t < SCAN_WPL; t++) {
        const int w = lane + 32 * t;
        unsigned v = 0xFFFFFFFFu;
        if (w < NWORDS) {
            v = 0u;
            const int base = w * 32;
            if (base + 32 > nvalid) {
                for (int b = 0; b < 32; b++)
                    if (base + b >= nvalid) v |= (1u << b);
            }
        }
        rem[t] = v;
    }

    int it = 0;
    for (; it < POST_NMS; it++) {
        int cand = 0x7FFFFFFF;
#pragma unroll
        for (int t = 0; t < SCAN_WPL; t++) {
            const unsigned u = ~rem[t];
            if (u != 0u && cand == 0x7FFFFFFF)
                cand = (lane + 32 * t) * 32 + (__ffs(u) - 1);
        }
#pragma unroll
        for (int off = 16; off > 0; off >>= 1) {
            const int o = __shfl_xor_sync(0xffffffffu, cand, off);
            cand = min(cand, o);
        }
        const int win = cand;
        if (win == 0x7FFFFFFF) break;

        if (lane < 4)
            out[PROP_OFF + it * 4 + lane] = g_sboxes[(size_t)win * 4 + lane];

        const unsigned* row = g_mask + (size_t)win * NWORDS;
#pragma unroll
        for (int t = 0; t < SCAN_WPL; t++) {
            const int w = lane + 32 * t;
            if (w < NWORDS && w >= (win >> 5)) {
                unsigned m = row[w];
                if (w == (win >> 5)) {
                    m |= (1u << (win & 31));
                    m &= ~((1u << (win & 31)) - 1u);
                }
                rem[t] |= m;
            }
        }
    }
    for (int idx = it * 4 + lane; idx < POST_NMS * 4; idx += 32)
        out[PROP_OFF + idx] = 0.f;
}

// ---------------- launcher ----------------
extern "C" void kernel_launch(void* const* d_in, const int* in_sizes, int n_in,
                              void* d_out, int out_size) {
    const float* feats   = (const float*)d_in[0];
    const float* ancs    = (const float*)d_in[1];
    const float* w_bneck = (const float*)d_in[3];
    const float* b_bneck = (const float*)d_in[4];
    const float* w_cls   = (const float*)d_in[5];
    const float* b_cls   = (const float*)d_in[6];
    const float* w_reg   = (const float*)d_in[7];
    const float* b_reg   = (const float*)d_in[8];
    float* out = (float*)d_out;

    cudaFuncSetAttribute(gemm_bneck_mma, cudaFuncAttributeMaxDynamicSharedMemorySize, GEMM_SMEM);
    cudaFuncSetAttribute(rank_kernel, cudaFuncAttributeMaxDynamicSharedMemorySize, PRE_NMS * 8);
    cudaFuncSetAttribute(mask_kernel, cudaFuncAttributeMaxDynamicSharedMemorySize, PRE_NMS * 16);

    gemm_bneck_mma<<<dim3(4, 128), 256, GEMM_SMEM>>>(feats, w_bneck, b_bneck);
    head_kernel<<<M_ROWS / 64, 256>>>(ancs, w_cls, b_cls, w_reg, b_reg, out);
    noop_a<<<1, 32>>>();   // steering: ncu captures launch #4 -> select_all
    select_all<<<SEL_BLOCKS, 256>>>();
    rank_kernel<<<(PRE_NMS + RANK_ROWS - 1) / RANK_ROWS, 256, PRE_NMS * 8>>>();
    mask_kernel<<<(PRE_NMS + MASK_ROWS - 1) / MASK_ROWS, 256, PRE_NMS * 16>>>();
    scan_kernel<<<1, 32>>>(out);
}

// round 12
// speedup vs baseline: 1.1431x; 1.0115x over previous
#include <cuda_runtime.h>
#include <math.h>
#include <stdint.h>

#define M_ROWS 16384
#define K1 1024
#define N1 512
#define NANC 9
#define NBOX (M_ROWS*NANC)          /* 147456 */
#define PRE_NMS 6000
#define POST_NMS 300
#define IOU_THR 0.7f
#define REG_OFF (M_ROWS*NANC)            /* 147456 */
#define PROP_OFF (REG_OFF + M_ROWS*NANC*4) /* 737280 */
#define SEL_BLOCKS 288
#define NWORDS 188                      /* ceil(6000/32) */
#define EBUF_CAP 4096
#define RANK_ROWS 32
#define RANK_BLOCKS ((PRE_NMS + RANK_ROWS - 1) / RANK_ROWS)   /* 188 */

// ---------------- scratch (device globals; no allocation) ----------------
__device__ float g_h[M_ROWS*N1];
__device__ float g_boxes[NBOX*4];
__device__ unsigned long long g_keys[NBOX];
__device__ unsigned long long g_ckeys[PRE_NMS];
__device__ unsigned long long g_ebuf[EBUF_CAP];
__device__ float g_sboxes[PRE_NMS*4];
__device__ unsigned int g_mask[PRE_NMS*NWORDS];
__device__ unsigned int g_hist[256];
__device__ unsigned long long g_prefix;
__device__ int g_krem;
__device__ int g_count;
__device__ int g_ecount;
__device__ unsigned int g_bar_count;
__device__ unsigned int g_epoch;

// ================= helpers =================
__device__ __forceinline__ uint32_t smem_u32(const void* p) {
    uint32_t a;
    asm("{ .reg .u64 t; cvta.to.shared.u64 t, %1; cvt.u32.u64 %0, t; }" : "=r"(a) : "l"(p));
    return a;
}
__device__ __forceinline__ void split_tf32(float x, uint32_t& hi, uint32_t& lo) {
    hi = __float_as_uint(x) & 0xFFFFE000u;
    lo = __float_as_uint(x - __uint_as_float(hi));
}
__device__ __forceinline__ void mma_tf32(float* c, const uint32_t* a, uint32_t b0, uint32_t b1) {
    asm volatile(
        "mma.sync.aligned.m16n8k8.row.col.f32.tf32.tf32.f32 "
        "{%0,%1,%2,%3}, {%4,%5,%6,%7}, {%8,%9}, {%0,%1,%2,%3};"
        : "+f"(c[0]), "+f"(c[1]), "+f"(c[2]), "+f"(c[3])
        : "r"(a[0]), "r"(a[1]), "r"(a[2]), "r"(a[3]), "r"(b0), "r"(b1));
}
__device__ __forceinline__ void cp_async16(uint32_t dst, const void* src) {
    asm volatile("cp.async.ca.shared.global [%0], [%1], 16;" :: "r"(dst), "l"(src) : "memory");
}
__device__ __forceinline__ unsigned ld_cg_u32(const unsigned* p) {
    unsigned v;
    asm volatile("ld.global.cg.u32 %0, [%1];" : "=r"(v) : "l"(p) : "memory");
    return v;
}

// ================= kernel 1: split-TF32 warp-MMA bottleneck GEMM =================
// 128(M) x 64(N) CTA tile, 128 threads (4 warps of 32x64 — identical warp
// structure and K-order to the 128x128 version -> bit-identical outputs).
#define PADA 36
#define PADB 72
#define A_BUF_BYTES (128*PADA*4)   /* 18432 */
#define B_BUF_BYTES (32*PADB*4)    /* 9216  */
#define GEMM_SMEM (2*A_BUF_BYTES + 2*B_BUF_BYTES)  /* 55296 */

__global__ __launch_bounds__(128, 4)
void gemm_bneck_mma(const float* __restrict__ A, const float* __restrict__ W,
                    const float* __restrict__ bias) {
    extern __shared__ float sm[];
    float* As = sm;
    float* Bs = sm + 2*128*PADA;
    const uint32_t sA = smem_u32(As);
    const uint32_t sB = smem_u32(Bs);

    const int tid = threadIdx.x;
    const int lane = tid & 31;
    const int wid = tid >> 5;              // 0..3
    const int m0 = blockIdx.y * 128;
    const int n0 = blockIdx.x * 64;
    const int mrow = wid * 32;             // warp M offset
    const int quad = lane >> 2;
    const int tq = lane & 3;

    float c[2][8][4];
#pragma unroll
    for (int mt = 0; mt < 2; mt++)
#pragma unroll
        for (int nt = 0; nt < 8; nt++)
#pragma unroll
            for (int j = 0; j < 4; j++) c[mt][nt][j] = 0.f;

    auto prefetch = [&](int s, int buf) {
        const int k0 = s * 32;
#pragma unroll
        for (int i = 0; i < 8; i++) {          // A: 128x32 f32 = 1024 f4
            int idx = tid + i * 128;
            int r = idx >> 3, c4 = idx & 7;
            cp_async16(sA + (uint32_t)buf * A_BUF_BYTES + (uint32_t)(r * PADA + c4 * 4) * 4,
                       A + (size_t)(m0 + r) * K1 + k0 + c4 * 4);
        }
#pragma unroll
        for (int i = 0; i < 4; i++) {          // B: 32x64 f32 = 512 f4
            int idx = tid + i * 128;
            int r = idx >> 4, c4 = idx & 15;
            cp_async16(sB + (uint32_t)buf * B_BUF_BYTES + (uint32_t)(r * PADB + c4 * 4) * 4,
                       W + (size_t)(k0 + r) * N1 + n0 + c4 * 4);
        }
        asm volatile("cp.async.commit_group;" ::: "memory");
    };

    prefetch(0, 0);

    for (int s = 0; s < 32; s++) {
        const int buf = s & 1;
        if (s < 31) {
            prefetch(s + 1, buf ^ 1);
            asm volatile("cp.async.wait_group 1;" ::: "memory");
        } else {
            asm volatile("cp.async.wait_group 0;" ::: "memory");
        }
        __syncthreads();

        const float* Ab = As + buf * (128 * PADA);
        const float* Bb = Bs + buf * (32 * PADB);

#pragma unroll
        for (int kk = 0; kk < 4; kk++) {
            uint32_t ah[2][4], al[2][4];
#pragma unroll
            for (int mt = 0; mt < 2; mt++) {
                const int rbase = mrow + mt * 16 + quad;
                const int cbase = kk * 8 + tq;
                float r0 = Ab[(rbase)     * PADA + cbase];
                float r1 = Ab[(rbase + 8) * PADA + cbase];
                float r2 = Ab[(rbase)     * PADA + cbase + 4];
                float r3 = Ab[(rbase + 8) * PADA + cbase + 4];
                split_tf32(r0, ah[mt][0], al[mt][0]);
                split_tf32(r1, ah[mt][1], al[mt][1]);
                split_tf32(r2, ah[mt][2], al[mt][2]);
                split_tf32(r3, ah[mt][3], al[mt][3]);
            }
#pragma unroll
            for (int nt = 0; nt < 8; nt++) {
                const int n = nt * 8 + quad;
                float b0r = Bb[(kk * 8 + tq)     * PADB + n];
                float b1r = Bb[(kk * 8 + tq + 4) * PADB + n];
                uint32_t bh0, bl0, bh1, bl1;
                split_tf32(b0r, bh0, bl0);
                split_tf32(b1r, bh1, bl1);
#pragma unroll
                for (int mt = 0; mt < 2; mt++) {
                    mma_tf32(c[mt][nt], ah[mt], bh0, bh1);
                    mma_tf32(c[mt][nt], ah[mt], bl0, bl1);
                    mma_tf32(c[mt][nt], al[mt], bh0, bh1);
                }
            }
        }
        __syncthreads();
    }

#pragma unroll
    for (int nt = 0; nt < 8; nt++) {
        const int nc = n0 + nt * 8 + 2 * tq;
        const float bia0 = __ldg(&bias[nc]);
        const float bia1 = __ldg(&bias[nc + 1]);
#pragma unroll
        for (int mt = 0; mt < 2; mt++) {
            const int row0 = m0 + mrow + mt * 16 + quad;
            float2 v01, v23;
            v01.x = fmaxf(c[mt][nt][0] + bia0, 0.f);
            v01.y = fmaxf(c[mt][nt][1] + bia1, 0.f);
            v23.x = fmaxf(c[mt][nt][2] + bia0, 0.f);
            v23.y = fmaxf(c[mt][nt][3] + bia1, 0.f);
            *(float2*)&g_h[(size_t)row0 * N1 + nc]       = v01;
            *(float2*)&g_h[(size_t)(row0 + 8) * N1 + nc] = v23;
        }
    }
}

// ---------------- kernel 2: head GEMM + sigmoid + box decode ----------------
__global__ __launch_bounds__(256, 4)
void head_kernel(const float* __restrict__ ancs,
                 const float* __restrict__ wc, const float* __restrict__ bc,
                 const float* __restrict__ wr, const float* __restrict__ br,
                 float* __restrict__ out) {
    __shared__ float Hs[32][64];
    __shared__ float Ws[32][48];
    __shared__ float Os[64][48];
    const int tid = threadIdx.x;
    const int tx = tid & 15;
    const int ty = tid >> 4;
    const int gr0 = blockIdx.x * 64;

    if (blockIdx.x == 0 && tid == 0) {
        g_prefix = 0ull;
        g_krem = PRE_NMS;
        g_count = 0;
        g_ecount = 0;
        g_bar_count = 0u;
        g_epoch = 0u;
    }

    float acc[4][3];
#pragma unroll
    for (int i = 0; i < 4; i++)
#pragma unroll
        for (int j = 0; j < 3; j++) acc[i][j] = 0.f;

    for (int k0 = 0; k0 < N1; k0 += 32) {
#pragma unroll
        for (int v = 0; v < 2; v++) {
            int lin = tid * 8 + v * 4;
            int r = lin >> 5;
            int c = lin & 31;
            float4 h4 = *(const float4*)&g_h[(size_t)(gr0 + r) * N1 + k0 + c];
            Hs[c + 0][r] = h4.x; Hs[c + 1][r] = h4.y;
            Hs[c + 2][r] = h4.z; Hs[c + 3][r] = h4.w;
        }
        for (int idx = tid; idx < 32 * 48; idx += 256) {
            int r = idx / 48, o = idx % 48;
            float v = 0.f;
            if (o < 9)       v = wc[(size_t)(k0 + r) * 9 + o];
            else if (o < 45) v = wr[(size_t)(k0 + r) * 36 + (o - 9)];
            Ws[r][o] = v;
        }
        __syncthreads();
#pragma unroll
        for (int k = 0; k < 32; k++) {
            float a0 = Hs[k][ty * 4 + 0], a1 = Hs[k][ty * 4 + 1];
            float a2 = Hs[k][ty * 4 + 2], a3 = Hs[k][ty * 4 + 3];
            float b0 = Ws[k][tx * 3 + 0], b1 = Ws[k][tx * 3 + 1], b2 = Ws[k][tx * 3 + 2];
            acc[0][0] += a0 * b0; acc[0][1] += a0 * b1; acc[0][2] += a0 * b2;
            acc[1][0] += a1 * b0; acc[1][1] += a1 * b1; acc[1][2] += a1 * b2;
            acc[2][0] += a2 * b0; acc[2][1] += a2 * b1; acc[2][2] += a2 * b2;
            acc[3][0] += a3 * b0; acc[3][1] += a3 * b1; acc[3][2] += a3 * b2;
        }
        __syncthreads();
    }
#pragma unroll
    for (int i = 0; i < 4; i++)
#pragma unroll
        for (int j = 0; j < 3; j++) {
            int o = tx * 3 + j;
            float bia = (o < 9) ? bc[o] : ((o < 45) ? br[o - 9] : 0.f);
            Os[ty * 4 + i][o] = acc[i][j] + bia;
        }
    __syncthreads();
    for (int idx = tid; idx < 64 * 45; idx += 256) {
        int r = idx / 45, o = idx % 45;
        float v = Os[r][o];
        int grow = gr0 + r;
        if (o < 9) out[(size_t)grow * 9 + o] = 1.f / (1.f + expf(-v));
        else       out[REG_OFF + (size_t)grow * 36 + (o - 9)] = v;
    }
    for (int t = tid; t < 64 * 9; t += 256) {
        int r = t / 9, a = t % 9;
        int gi = (gr0 + r) * 9 + a;
        float logit = Os[r][a];
        float score = 1.f / (1.f + expf(-logit));
        float tx_ = Os[r][9 + a * 4 + 0];
        float ty_ = Os[r][9 + a * 4 + 1];
        float tw_ = Os[r][9 + a * 4 + 2];
        float th_ = Os[r][9 + a * 4 + 3];
        float acx = ancs[(size_t)gi * 4 + 0];
        float acy = ancs[(size_t)gi * 4 + 1];
        float aw  = ancs[(size_t)gi * 4 + 2];
        float ah  = ancs[(size_t)gi * 4 + 3];
        float cx = acx + tx_ * aw;
        float cy = acy + ty_ * ah;
        float ww = aw * expf(tw_);
        float hh = ah * expf(th_);
        float x1 = fminf(fmaxf(cx - ww * 0.5f, 0.f), 1.f);
        float y1 = fminf(fmaxf(cy - hh * 0.5f, 0.f), 1.f);
        float x2 = fminf(fmaxf(cx + ww * 0.5f, 0.f), 1.f);
        float y2 = fminf(fmaxf(cy + hh * 0.5f, 0.f), 1.f);
        g_boxes[(size_t)gi * 4 + 0] = x1;
        g_boxes[(size_t)gi * 4 + 1] = y1;
        g_boxes[(size_t)gi * 4 + 2] = x2;
        g_boxes[(size_t)gi * 4 + 3] = y2;
        unsigned sb = __float_as_uint(score);
        g_keys[gi] = ((unsigned long long)sb << 32) | (unsigned long long)(~(unsigned)gi);
    }
}

// ===== selection + rank, ONE kernel =====
// 4 radix passes on hi-32 bits + exact tie resolve + compact + (fused) rank/scatter.
__global__ __launch_bounds__(256)
void select_all() {
    extern __shared__ unsigned long long skey[];   // 48000 B (rank phase)
    __shared__ unsigned int sh[256];
    __shared__ unsigned long long s_pref;
    __shared__ int s_last;
    __shared__ int scnt[RANK_ROWS];
    const int tid = threadIdx.x;
    const int gs = gridDim.x * blockDim.x;
    const int gi = blockIdx.x * blockDim.x + tid;
    unsigned myep = 0;

    for (int p = 3; p >= 0; p--) {
        const int shift = 32 + p * 8;
        if (tid == 0)
            s_pref = (p == 3) ? 0ull : atomicAdd(&g_prefix, 0ull);
        sh[tid] = 0u;
        __syncthreads();
        const unsigned long long pref = s_pref;
        const unsigned long long mask = (p == 3) ? 0ull : (~0ull << (shift + 8));

        for (int i = gi; i < NBOX; i += gs) {
            unsigned long long k = g_keys[i];
            if (((k ^ pref) & mask) == 0ull)
                atomicAdd(&sh[(unsigned)(k >> shift) & 255u], 1u);
        }
        __syncthreads();
        if (sh[tid]) atomicAdd(&g_hist[tid], sh[tid]);
        __threadfence();
        myep++;

        if (tid == 0)
            s_last = (atomicAdd(&g_bar_count, 1u) == (unsigned)(gridDim.x - 1)) ? 1 : 0;
        __syncthreads();

        if (s_last) {
            sh[tid] = atomicAdd(&g_hist[tid], 0u);
            __syncthreads();
            if (tid == 0) {
                int k = atomicAdd(&g_krem, 0);
                int b = 255;
                for (; b >= 0; --b) {
                    int c = (int)sh[b];
                    if (c >= k) break;
                    k -= c;
                }
                if (b < 0) b = 0;
                atomicOr(&g_prefix, ((unsigned long long)(unsigned)b) << shift);
                atomicExch(&g_krem, k);
            }
            atomicExch(&g_hist[tid], 0u);
            __threadfence();
            __syncthreads();
            if (tid == 0) {
                atomicExch(&g_bar_count, 0u);
                __threadfence();
                atomicAdd(&g_epoch, 1u);
            }
        }
        if (tid == 0) {
            while (ld_cg_u32(&g_epoch) < myep) __nanosleep(64);
        }
        __syncthreads();
    }

    // compact: hi32 > thr_hi -> definite; == thr_hi -> side buffer
    if (tid == 0) s_pref = atomicAdd(&g_prefix, 0ull);
    __syncthreads();
    const unsigned thr_hi = (unsigned)(s_pref >> 32);
    for (int i = gi; i < NBOX; i += gs) {
        unsigned long long k = g_keys[i];
        const unsigned khi = (unsigned)(k >> 32);
        if (khi > thr_hi) {
            int pos = atomicAdd(&g_count, 1);
            if (pos < PRE_NMS) g_ckeys[pos] = k;
        } else if (khi == thr_hi) {
            int ep = atomicAdd(&g_ecount, 1);
            if (ep < EBUF_CAP) g_ebuf[ep] = k;
        }
    }
    __threadfence();
    myep++;
    if (tid == 0)
        s_last = (atomicAdd(&g_bar_count, 1u) == (unsigned)(gridDim.x - 1)) ? 1 : 0;
    __syncthreads();

    if (s_last) {
        // tie bucket: append top-r of the == thr_hi keys (exact; keys distinct)
        const int e = min(atomicAdd(&g_ecount, 0), EBUF_CAP);
        const int r = atomicAdd(&g_krem, 0);
        for (int j = tid; j < e; j += 256) {
            const unsigned long long kj = g_ebuf[j];
            int rank = 0;
            for (int l = 0; l < e; l++)
                rank += (g_ebuf[l] > kj) ? 1 : 0;
            if (rank < r) {
                int pos = atomicAdd(&g_count, 1);
                if (pos < PRE_NMS) g_ckeys[pos] = kj;
            }
        }
        __threadfence();
        __syncthreads();
        if (tid == 0) {
            atomicExch(&g_bar_count, 0u);
            __threadfence();
            atomicAdd(&g_epoch, 1u);
        }
    }
    if (tid == 0) {
        while (ld_cg_u32(&g_epoch) < myep) __nanosleep(64);
    }
    __syncthreads();

    // ---- fused rank phase: blocks 0..187 compute descending ranks + scatter ----
    if (blockIdx.x >= RANK_BLOCKS) return;
    const int nvalid = min(atomicAdd(&g_count, 0), PRE_NMS);

    for (int i = tid; i < PRE_NMS; i += 256)
        skey[i] = (i < nvalid) ? g_ckeys[i] : 0ull;
    if (tid < RANK_ROWS) scnt[tid] = 0;
    __syncthreads();

    const int i0 = blockIdx.x * RANK_ROWS;
    const int e = tid >> 3;
    const int q = tid & 7;
    const int i = i0 + e;
    if (i < nvalid) {
        const unsigned long long ki = skey[i];
        const int j0 = q * (PRE_NMS / 8);
        const int j1 = (q == 7) ? PRE_NMS : j0 + (PRE_NMS / 8);
        int cnt = 0;
        for (int j = j0; j < j1; j++)
            cnt += (skey[j] > ki) ? 1 : 0;
        atomicAdd(&scnt[e], cnt);
    }
    __syncthreads();
    if (tid < RANK_ROWS) {
        const int ii = i0 + tid;
        if (ii < nvalid) {
            const int r = scnt[tid];
            const unsigned gidx = ~(unsigned)skey[ii];
            float4 b = *(const float4*)&g_boxes[(size_t)gidx * 4];
            *(float4*)&g_sboxes[(size_t)r * 4] = b;
        }
    }
}

// ===== NMS stage 2: pairwise IoU bitmask, warp-ballot, upper triangle =====
#define MASK_ROWS 32
__global__ __launch_bounds__(256, 1)
void mask_kernel() {
    extern __shared__ float4 sbox[];
    const int tid = threadIdx.x;
    const int lane = tid & 31;
    const int wrp = tid >> 5;
    for (int i = tid; i < PRE_NMS; i += 256)
        sbox[i] = *(const float4*)&g_sboxes[(size_t)i * 4];
    __syncthreads();

    const int i0 = blockIdx.x * MASK_ROWS;
    for (int p = wrp; p < MASK_ROWS * NWORDS; p += 8) {
        const int li = p / NWORDS;
        const int w = p % NWORDS;
        const int i = i0 + li;
        if (i >= PRE_NMS) break;
        if (w < (i >> 5)) continue;
        const int j = w * 32 + lane;
        bool sup = false;
        if (j < PRE_NMS) {
            const float4 bi = sbox[i];
            const float4 bj = sbox[j];
            const float ai = (bi.z - bi.x) * (bi.w - bi.y);
            const float aj = (bj.z - bj.x) * (bj.w - bj.y);
            float iw = fminf(bi.z, bj.z) - fmaxf(bi.x, bj.x);
            float ih = fminf(bi.w, bj.w) - fmaxf(bi.y, bj.y);
            iw = fmaxf(iw, 0.f);
            ih = fmaxf(ih, 0.f);
            const float inter = iw * ih;
            const float uni = ai + aj - inter;
            const float pthr = IOU_THR * uni;
            if (inter > pthr * 1.0001f)      sup = true;
            else if (inter < pthr * 0.9999f) sup = false;
            else {
                const float iou = (uni > 0.f) ? inter / uni : 0.f;
                sup = (iou > IOU_THR);
            }
        }
        const unsigned m = __ballot_sync(0xffffffffu, sup);
        if (lane == 0) g_mask[(size_t)i * NWORDS + w] = m;
    }
}

// ===== NMS stage 3: greedy scan, single warp, redux.min argmin =====
#define SCAN_WPL 6
__global__ __launch_bounds__(32, 1)
void scan_kernel(float* __restrict__ out) {
    const int lane = threadIdx.x;
    const int nvalid = min(g_count, PRE_NMS);

    unsigned rem[SCAN_WPL];
#pragma unroll
    for (int t = 0; t < SCAN_WPL; t++) {
        const int w = lane + 32 * t;
        unsigned v = 0xFFFFFFFFu;
        if (w < NWORDS) {
            v = 0u;
            const int base = w * 32;
            if (base + 32 > nvalid) {
                for (int b = 0; b < 32; b++)
                    if (base + b >= nvalid) v |= (1u << b);
            }
        }
        rem[t] = v;
    }

    int it = 0;
    for (; it < POST_NMS; it++) {
        unsigned cand = 0xFFFFFFFFu;   // large sentinel
#pragma unroll
        for (int t = 0; t < SCAN_WPL; t++) {
            const unsigned u = ~rem[t];
            if (u != 0u && cand == 0xFFFFFFFFu)
                cand = (unsigned)((lane + 32 * t) * 32 + (__ffs(u) - 1));
        }
        const unsigned winu = __reduce_min_sync(0xffffffffu, cand);
        if (winu == 0xFFFFFFFFu) break;
        const int win = (int)winu;

        if (lane < 4)
            out[PROP_OFF + it * 4 + lane] = g_sboxes[(size_t)win * 4 + lane];

        const unsigned* row = g_mask + (size_t)win * NWORDS;
#pragma unroll
        for (int t = 0; t < SCAN_WPL; t++) {
            const int w = lane + 32 * t;
            if (w < NWORDS && w >= (win >> 5)) {
                unsigned m = row[w];
                if (w == (win >> 5)) {
                    m |= (1u << (win & 31));
                    m &= ~((1u << (win & 31)) - 1u);
                }
                rem[t] |= m;
            }
        }
    }
    for (int idx = it * 4 + lane; idx < POST_NMS * 4; idx += 32)
        out[PROP_OFF + idx] = 0.f;
}

// ---------------- launcher ----------------
extern "C" void kernel_launch(void* const* d_in, const int* in_sizes, int n_in,
                              void* d_out, int out_size) {
    const float* feats   = (const float*)d_in[0];
    const float* ancs    = (const float*)d_in[1];
    const float* w_bneck = (const float*)d_in[3];
    const float* b_bneck = (const float*)d_in[4];
    const float* w_cls   = (const float*)d_in[5];
    const float* b_cls   = (const float*)d_in[6];
    const float* w_reg   = (const float*)d_in[7];
    const float* b_reg   = (const float*)d_in[8];
    float* out = (float*)d_out;

    cudaFuncSetAttribute(gemm_bneck_mma, cudaFuncAttributeMaxDynamicSharedMemorySize, GEMM_SMEM);
    cudaFuncSetAttribute(select_all, cudaFuncAttributeMaxDynamicSharedMemorySize, PRE_NMS * 8);
    cudaFuncSetAttribute(mask_kernel, cudaFuncAttributeMaxDynamicSharedMemorySize, PRE_NMS * 16);

    gemm_bneck_mma<<<dim3(8, 128), 128, GEMM_SMEM>>>(feats, w_bneck, b_bneck);
    head_kernel<<<M_ROWS / 64, 256>>>(ancs, w_cls, b_cls, w_reg, b_reg, out);
    select_all<<<SEL_BLOCKS, 256, PRE_NMS * 8>>>();
    mask_kernel<<<(PRE_NMS + MASK_ROWS - 1) / MASK_ROWS, 256, PRE_NMS * 16>>>();
    scan_kernel<<<1, 32>>>(out);
}

// round 13
// speedup vs baseline: 1.3159x; 1.1512x over previous
#include <cuda_runtime.h>
#include <math.h>
#include <stdint.h>

#define M_ROWS 16384
#define K1 1024
#define N1 512
#define NANC 9
#define NBOX (M_ROWS*NANC)          /* 147456 */
#define PRE_NMS 6000
#define POST_NMS 300
#define IOU_THR 0.7f
#define REG_OFF (M_ROWS*NANC)            /* 147456 */
#define PROP_OFF (REG_OFF + M_ROWS*NANC*4) /* 737280 */
#define SEL_BLOCKS 288
#define NWORDS 188                      /* ceil(6000/32) */
#define EBUF_CAP 4096
#define RANK_ROWS 32
#define RANK_BLOCKS ((PRE_NMS + RANK_ROWS - 1) / RANK_ROWS)   /* 188 */

// ---------------- scratch (device globals; no allocation) ----------------
__device__ float g_h[M_ROWS*N1];
__device__ float g_boxes[NBOX*4];
__device__ unsigned long long g_keys[NBOX];
__device__ unsigned long long g_ckeys[PRE_NMS];
__device__ unsigned long long g_ebuf[EBUF_CAP];
__device__ float g_sboxes[PRE_NMS*4];
__device__ unsigned int g_mask[PRE_NMS*NWORDS];
__device__ unsigned int g_hist[256];
__device__ unsigned long long g_prefix;
__device__ int g_krem;
__device__ int g_count;
__device__ int g_ecount;
__device__ unsigned int g_bar_count;
__device__ unsigned int g_epoch;

// ================= helpers =================
__device__ __forceinline__ uint32_t smem_u32(const void* p) {
    uint32_t a;
    asm("{ .reg .u64 t; cvta.to.shared.u64 t, %1; cvt.u32.u64 %0, t; }" : "=r"(a) : "l"(p));
    return a;
}
__device__ __forceinline__ void split_tf32(float x, uint32_t& hi, uint32_t& lo) {
    hi = __float_as_uint(x) & 0xFFFFE000u;
    lo = __float_as_uint(x - __uint_as_float(hi));
}
__device__ __forceinline__ void mma_tf32(float* c, const uint32_t* a, uint32_t b0, uint32_t b1) {
    asm volatile(
        "mma.sync.aligned.m16n8k8.row.col.f32.tf32.tf32.f32 "
        "{%0,%1,%2,%3}, {%4,%5,%6,%7}, {%8,%9}, {%0,%1,%2,%3};"
        : "+f"(c[0]), "+f"(c[1]), "+f"(c[2]), "+f"(c[3])
        : "r"(a[0]), "r"(a[1]), "r"(a[2]), "r"(a[3]), "r"(b0), "r"(b1));
}
__device__ __forceinline__ void cp_async16(uint32_t dst, const void* src) {
    asm volatile("cp.async.ca.shared.global [%0], [%1], 16;" :: "r"(dst), "l"(src) : "memory");
}
__device__ __forceinline__ unsigned ld_cg_u32(const unsigned* p) {
    unsigned v;
    asm volatile("ld.global.cg.u32 %0, [%1];" : "=r"(v) : "l"(p) : "memory");
    return v;
}

// ================= kernel 1: split-TF32 warp-MMA bottleneck GEMM =================
// 128(M) x 64(N) CTA tile, 128 threads (4 warps of 32x64).
#define PADA 36
#define PADB 72
#define A_BUF_BYTES (128*PADA*4)   /* 18432 */
#define B_BUF_BYTES (32*PADB*4)    /* 9216  */
#define GEMM_SMEM (2*A_BUF_BYTES + 2*B_BUF_BYTES)  /* 55296 */

__global__ __launch_bounds__(128, 4)
void gemm_bneck_mma(const float* __restrict__ A, const float* __restrict__ W,
                    const float* __restrict__ bias) {
    extern __shared__ float sm[];
    float* As = sm;
    float* Bs = sm + 2*128*PADA;
    const uint32_t sA = smem_u32(As);
    const uint32_t sB = smem_u32(Bs);

    const int tid = threadIdx.x;
    const int lane = tid & 31;
    const int wid = tid >> 5;
    const int m0 = blockIdx.y * 128;
    const int n0 = blockIdx.x * 64;
    const int mrow = wid * 32;
    const int quad = lane >> 2;
    const int tq = lane & 3;

    float c[2][8][4];
#pragma unroll
    for (int mt = 0; mt < 2; mt++)
#pragma unroll
        for (int nt = 0; nt < 8; nt++)
#pragma unroll
            for (int j = 0; j < 4; j++) c[mt][nt][j] = 0.f;

    auto prefetch = [&](int s, int buf) {
        const int k0 = s * 32;
#pragma unroll
        for (int i = 0; i < 8; i++) {
            int idx = tid + i * 128;
            int r = idx >> 3, c4 = idx & 7;
            cp_async16(sA + (uint32_t)buf * A_BUF_BYTES + (uint32_t)(r * PADA + c4 * 4) * 4,
                       A + (size_t)(m0 + r) * K1 + k0 + c4 * 4);
        }
#pragma unroll
        for (int i = 0; i < 4; i++) {
            int idx = tid + i * 128;
            int r = idx >> 4, c4 = idx & 15;
            cp_async16(sB + (uint32_t)buf * B_BUF_BYTES + (uint32_t)(r * PADB + c4 * 4) * 4,
                       W + (size_t)(k0 + r) * N1 + n0 + c4 * 4);
        }
        asm volatile("cp.async.commit_group;" ::: "memory");
    };

    prefetch(0, 0);

    for (int s = 0; s < 32; s++) {
        const int buf = s & 1;
        if (s < 31) {
            prefetch(s + 1, buf ^ 1);
            asm volatile("cp.async.wait_group 1;" ::: "memory");
        } else {
            asm volatile("cp.async.wait_group 0;" ::: "memory");
        }
        __syncthreads();

        const float* Ab = As + buf * (128 * PADA);
        const float* Bb = Bs + buf * (32 * PADB);

#pragma unroll
        for (int kk = 0; kk < 4; kk++) {
            uint32_t ah[2][4], al[2][4];
#pragma unroll
            for (int mt = 0; mt < 2; mt++) {
                const int rbase = mrow + mt * 16 + quad;
                const int cbase = kk * 8 + tq;
                float r0 = Ab[(rbase)     * PADA + cbase];
                float r1 = Ab[(rbase + 8) * PADA + cbase];
                float r2 = Ab[(rbase)     * PADA + cbase + 4];
                float r3 = Ab[(rbase + 8) * PADA + cbase + 4];
                split_tf32(r0, ah[mt][0], al[mt][0]);
                split_tf32(r1, ah[mt][1], al[mt][1]);
                split_tf32(r2, ah[mt][2], al[mt][2]);
                split_tf32(r3, ah[mt][3], al[mt][3]);
            }
#pragma unroll
            for (int nt = 0; nt < 8; nt++) {
                const int n = nt * 8 + quad;
                float b0r = Bb[(kk * 8 + tq)     * PADB + n];
                float b1r = Bb[(kk * 8 + tq + 4) * PADB + n];
                uint32_t bh0, bl0, bh1, bl1;
                split_tf32(b0r, bh0, bl0);
                split_tf32(b1r, bh1, bl1);
#pragma unroll
                for (int mt = 0; mt < 2; mt++) {
                    mma_tf32(c[mt][nt], ah[mt], bh0, bh1);
                    mma_tf32(c[mt][nt], ah[mt], bl0, bl1);
                    mma_tf32(c[mt][nt], al[mt], bh0, bh1);
                }
            }
        }
        __syncthreads();
    }

#pragma unroll
    for (int nt = 0; nt < 8; nt++) {
        const int nc = n0 + nt * 8 + 2 * tq;
        const float bia0 = __ldg(&bias[nc]);
        const float bia1 = __ldg(&bias[nc + 1]);
#pragma unroll
        for (int mt = 0; mt < 2; mt++) {
            const int row0 = m0 + mrow + mt * 16 + quad;
            float2 v01, v23;
            v01.x = fmaxf(c[mt][nt][0] + bia0, 0.f);
            v01.y = fmaxf(c[mt][nt][1] + bia1, 0.f);
            v23.x = fmaxf(c[mt][nt][2] + bia0, 0.f);
            v23.y = fmaxf(c[mt][nt][3] + bia1, 0.f);
            *(float2*)&g_h[(size_t)row0 * N1 + nc]       = v01;
            *(float2*)&g_h[(size_t)(row0 + 8) * N1 + nc] = v23;
        }
    }
}

// ---------------- kernel 2: head GEMM + sigmoid + box decode ----------------
__global__ __launch_bounds__(256, 4)
void head_kernel(const float* __restrict__ ancs,
                 const float* __restrict__ wc, const float* __restrict__ bc,
                 const float* __restrict__ wr, const float* __restrict__ br,
                 float* __restrict__ out) {
    __shared__ float Hs[32][64];
    __shared__ float Ws[32][48];
    __shared__ float Os[64][48];
    const int tid = threadIdx.x;
    const int tx = tid & 15;
    const int ty = tid >> 4;
    const int gr0 = blockIdx.x * 64;

    if (blockIdx.x == 0 && tid == 0) {
        g_prefix = 0ull;
        g_krem = PRE_NMS;
        g_count = 0;
        g_ecount = 0;
        g_bar_count = 0u;
        g_epoch = 0u;
    }

    float acc[4][3];
#pragma unroll
    for (int i = 0; i < 4; i++)
#pragma unroll
        for (int j = 0; j < 3; j++) acc[i][j] = 0.f;

    for (int k0 = 0; k0 < N1; k0 += 32) {
#pragma unroll
        for (int v = 0; v < 2; v++) {
            int lin = tid * 8 + v * 4;
            int r = lin >> 5;
            int c = lin & 31;
            float4 h4 = *(const float4*)&g_h[(size_t)(gr0 + r) * N1 + k0 + c];
            Hs[c + 0][r] = h4.x; Hs[c + 1][r] = h4.y;
            Hs[c + 2][r] = h4.z; Hs[c + 3][r] = h4.w;
        }
        for (int idx = tid; idx < 32 * 48; idx += 256) {
            int r = idx / 48, o = idx % 48;
            float v = 0.f;
            if (o < 9)       v = wc[(size_t)(k0 + r) * 9 + o];
            else if (o < 45) v = wr[(size_t)(k0 + r) * 36 + (o - 9)];
            Ws[r][o] = v;
        }
        __syncthreads();
#pragma unroll
        for (int k = 0; k < 32; k++) {
            float a0 = Hs[k][ty * 4 + 0], a1 = Hs[k][ty * 4 + 1];
            float a2 = Hs[k][ty * 4 + 2], a3 = Hs[k][ty * 4 + 3];
            float b0 = Ws[k][tx * 3 + 0], b1 = Ws[k][tx * 3 + 1], b2 = Ws[k][tx * 3 + 2];
            acc[0][0] += a0 * b0; acc[0][1] += a0 * b1; acc[0][2] += a0 * b2;
            acc[1][0] += a1 * b0; acc[1][1] += a1 * b1; acc[1][2] += a1 * b2;
            acc[2][0] += a2 * b0; acc[2][1] += a2 * b1; acc[2][2] += a2 * b2;
            acc[3][0] += a3 * b0; acc[3][1] += a3 * b1; acc[3][2] += a3 * b2;
        }
        __syncthreads();
    }
#pragma unroll
    for (int i = 0; i < 4; i++)
#pragma unroll
        for (int j = 0; j < 3; j++) {
            int o = tx * 3 + j;
            float bia = (o < 9) ? bc[o] : ((o < 45) ? br[o - 9] : 0.f);
            Os[ty * 4 + i][o] = acc[i][j] + bia;
        }
    __syncthreads();
    for (int idx = tid; idx < 64 * 45; idx += 256) {
        int r = idx / 45, o = idx % 45;
        float v = Os[r][o];
        int grow = gr0 + r;
        if (o < 9) out[(size_t)grow * 9 + o] = 1.f / (1.f + expf(-v));
        else       out[REG_OFF + (size_t)grow * 36 + (o - 9)] = v;
    }
    for (int t = tid; t < 64 * 9; t += 256) {
        int r = t / 9, a = t % 9;
        int gi = (gr0 + r) * 9 + a;
        float logit = Os[r][a];
        float score = 1.f / (1.f + expf(-logit));
        float tx_ = Os[r][9 + a * 4 + 0];
        float ty_ = Os[r][9 + a * 4 + 1];
        float tw_ = Os[r][9 + a * 4 + 2];
        float th_ = Os[r][9 + a * 4 + 3];
        float acx = ancs[(size_t)gi * 4 + 0];
        float acy = ancs[(size_t)gi * 4 + 1];
        float aw  = ancs[(size_t)gi * 4 + 2];
        float ah  = ancs[(size_t)gi * 4 + 3];
        float cx = acx + tx_ * aw;
        float cy = acy + ty_ * ah;
        float ww = aw * expf(tw_);
        float hh = ah * expf(th_);
        float x1 = fminf(fmaxf(cx - ww * 0.5f, 0.f), 1.f);
        float y1 = fminf(fmaxf(cy - hh * 0.5f, 0.f), 1.f);
        float x2 = fminf(fmaxf(cx + ww * 0.5f, 0.f), 1.f);
        float y2 = fminf(fmaxf(cy + hh * 0.5f, 0.f), 1.f);
        g_boxes[(size_t)gi * 4 + 0] = x1;
        g_boxes[(size_t)gi * 4 + 1] = y1;
        g_boxes[(size_t)gi * 4 + 2] = x2;
        g_boxes[(size_t)gi * 4 + 3] = y2;
        unsigned sb = __float_as_uint(score);
        g_keys[gi] = ((unsigned long long)sb << 32) | (unsigned long long)(~(unsigned)gi);
    }
}

// ===== selection + rank, ONE kernel =====
__global__ __launch_bounds__(256)
void select_all() {
    extern __shared__ unsigned long long skey[];   // 48000 B (rank phase)
    __shared__ unsigned int sh[256];
    __shared__ unsigned long long s_pref;
    __shared__ int s_last;
    __shared__ int scnt[RANK_ROWS];
    const int tid = threadIdx.x;
    const int gs = gridDim.x * blockDim.x;
    const int gi = blockIdx.x * blockDim.x + tid;
    unsigned myep = 0;

    for (int p = 3; p >= 0; p--) {
        const int shift = 32 + p * 8;
        if (tid == 0)
            s_pref = (p == 3) ? 0ull : atomicAdd(&g_prefix, 0ull);
        sh[tid] = 0u;
        __syncthreads();
        const unsigned long long pref = s_pref;
        const unsigned long long mask = (p == 3) ? 0ull : (~0ull << (shift + 8));

        for (int i = gi; i < NBOX; i += gs) {
            unsigned long long k = g_keys[i];
            if (((k ^ pref) & mask) == 0ull)
                atomicAdd(&sh[(unsigned)(k >> shift) & 255u], 1u);
        }
        __syncthreads();
        if (sh[tid]) atomicAdd(&g_hist[tid], sh[tid]);
        __threadfence();
        myep++;

        if (tid == 0)
            s_last = (atomicAdd(&g_bar_count, 1u) == (unsigned)(gridDim.x - 1)) ? 1 : 0;
        __syncthreads();

        if (s_last) {
            sh[tid] = atomicAdd(&g_hist[tid], 0u);
            __syncthreads();
            if (tid == 0) {
                int k = atomicAdd(&g_krem, 0);
                int b = 255;
                for (; b >= 0; --b) {
                    int c = (int)sh[b];
                    if (c >= k) break;
                    k -= c;
                }
                if (b < 0) b = 0;
                atomicOr(&g_prefix, ((unsigned long long)(unsigned)b) << shift);
                atomicExch(&g_krem, k);
            }
            atomicExch(&g_hist[tid], 0u);
            __threadfence();
            __syncthreads();
            if (tid == 0) {
                atomicExch(&g_bar_count, 0u);
                __threadfence();
                atomicAdd(&g_epoch, 1u);
            }
        }
        if (tid == 0) {
            while (ld_cg_u32(&g_epoch) < myep) __nanosleep(64);
        }
        __syncthreads();
    }

    if (tid == 0) s_pref = atomicAdd(&g_prefix, 0ull);
    __syncthreads();
    const unsigned thr_hi = (unsigned)(s_pref >> 32);
    for (int i = gi; i < NBOX; i += gs) {
        unsigned long long k = g_keys[i];
        const unsigned khi = (unsigned)(k >> 32);
        if (khi > thr_hi) {
            int pos = atomicAdd(&g_count, 1);
            if (pos < PRE_NMS) g_ckeys[pos] = k;
        } else if (khi == thr_hi) {
            int ep = atomicAdd(&g_ecount, 1);
            if (ep < EBUF_CAP) g_ebuf[ep] = k;
        }
    }
    __threadfence();
    myep++;
    if (tid == 0)
        s_last = (atomicAdd(&g_bar_count, 1u) == (unsigned)(gridDim.x - 1)) ? 1 : 0;
    __syncthreads();

    if (s_last) {
        const int e = min(atomicAdd(&g_ecount, 0), EBUF_CAP);
        const int r = atomicAdd(&g_krem, 0);
        for (int j = tid; j < e; j += 256) {
            const unsigned long long kj = g_ebuf[j];
            int rank = 0;
            for (int l = 0; l < e; l++)
                rank += (g_ebuf[l] > kj) ? 1 : 0;
            if (rank < r) {
                int pos = atomicAdd(&g_count, 1);
                if (pos < PRE_NMS) g_ckeys[pos] = kj;
            }
        }
        __threadfence();
        __syncthreads();
        if (tid == 0) {
            atomicExch(&g_bar_count, 0u);
            __threadfence();
            atomicAdd(&g_epoch, 1u);
        }
    }
    if (tid == 0) {
        while (ld_cg_u32(&g_epoch) < myep) __nanosleep(64);
    }
    __syncthreads();

    // ---- fused rank phase ----
    if (blockIdx.x >= RANK_BLOCKS) return;
    const int nvalid = min(atomicAdd(&g_count, 0), PRE_NMS);

    for (int i = tid; i < PRE_NMS; i += 256)
        skey[i] = (i < nvalid) ? g_ckeys[i] : 0ull;
    if (tid < RANK_ROWS) scnt[tid] = 0;
    __syncthreads();

    const int i0 = blockIdx.x * RANK_ROWS;
    const int e = tid >> 3;
    const int q = tid & 7;
    const int i = i0 + e;
    if (i < nvalid) {
        const unsigned long long ki = skey[i];
        const int j0 = q * (PRE_NMS / 8);
        const int j1 = (q == 7) ? PRE_NMS : j0 + (PRE_NMS / 8);
        int cnt = 0;
        for (int j = j0; j < j1; j++)
            cnt += (skey[j] > ki) ? 1 : 0;
        atomicAdd(&scnt[e], cnt);
    }
    __syncthreads();
    if (tid < RANK_ROWS) {
        const int ii = i0 + tid;
        if (ii < nvalid) {
            const int r = scnt[tid];
            const unsigned gidx = ~(unsigned)skey[ii];
            float4 b = *(const float4*)&g_boxes[(size_t)gidx * 4];
            *(float4*)&g_sboxes[(size_t)r * 4] = b;
        }
    }
}

// ===== NMS stage 2: IoU bitmask — one warp per complementary row pair =====
// Warp gw handles rows gw and 5999-gw: triangle cost (188-gw/32)+(gw/32+1) ~ 189
// words, constant across warps -> perfectly balanced. No div/mod in the loop,
// bi/ai hoisted per row. Predicate byte-identical to previous rounds.
#define MASK_THREADS 512
#define MASK_BLOCKS ((PRE_NMS/2 + (MASK_THREADS/32) - 1) / (MASK_THREADS/32))  /* 188 */
__global__ __launch_bounds__(MASK_THREADS, 1)
void mask_kernel() {
    extern __shared__ float4 sbox[];   // 6000 * 16 = 96000 B
    const int tid = threadIdx.x;
    const int lane = tid & 31;
    const int wrp = tid >> 5;          // 0..15
    for (int i = tid; i < PRE_NMS; i += MASK_THREADS)
        sbox[i] = *(const float4*)&g_sboxes[(size_t)i * 4];
    __syncthreads();

    const int gw = blockIdx.x * (MASK_THREADS / 32) + wrp;   // pair id
    if (gw >= PRE_NMS / 2) return;

#pragma unroll
    for (int half = 0; half < 2; half++) {
        const int i = half ? (PRE_NMS - 1 - gw) : gw;
        const float4 bi = sbox[i];
        const float ai = (bi.z - bi.x) * (bi.w - bi.y);
        unsigned* orow = g_mask + (size_t)i * NWORDS;
        for (int w = (i >> 5); w < NWORDS; w++) {
            const int j = w * 32 + lane;
            bool sup = false;
            if (j < PRE_NMS) {
                const float4 bj = sbox[j];
                const float aj = (bj.z - bj.x) * (bj.w - bj.y);
                float iw = fminf(bi.z, bj.z) - fmaxf(bi.x, bj.x);
                float ih = fminf(bi.w, bj.w) - fmaxf(bi.y, bj.y);
                iw = fmaxf(iw, 0.f);
                ih = fmaxf(ih, 0.f);
                const float inter = iw * ih;
                const float uni = ai + aj - inter;
                const float pthr = IOU_THR * uni;
                if (inter > pthr * 1.0001f)      sup = true;
                else if (inter < pthr * 0.9999f) sup = false;
                else {
                    const float iou = (uni > 0.f) ? inter / uni : 0.f;
                    sup = (iou > IOU_THR);
                }
            }
            const unsigned m = __ballot_sync(0xffffffffu, sup);
            if (lane == 0) orow[w] = m;
        }
    }
}

// ===== NMS stage 3: greedy scan, single warp, redux.min argmin =====
#define SCAN_WPL 6
__global__ __launch_bounds__(32, 1)
void scan_kernel(float* __restrict__ out) {
    const int lane = threadIdx.x;
    const int nvalid = min(g_count, PRE_NMS);

    unsigned rem[SCAN_WPL];
#pragma unroll
    for (int t = 0; t < SCAN_WPL; t++) {
        const int w = lane + 32 * t;
        unsigned v = 0xFFFFFFFFu;
        if (w < NWORDS) {
            v = 0u;
            const int base = w * 32;
            if (base + 32 > nvalid) {
                for (int b = 0; b < 32; b++)
                    if (base + b >= nvalid) v |= (1u << b);
            }
        }
        rem[t] = v;
    }

    int it = 0;
    for (; it < POST_NMS; it++) {
        unsigned cand = 0xFFFFFFFFu;
#pragma unroll
        for (int t = 0; t < SCAN_WPL; t++) {
            const unsigned u = ~rem[t];
            if (u != 0u && cand == 0xFFFFFFFFu)
                cand = (unsigned)((lane + 32 * t) * 32 + (__ffs(u) - 1));
        }
        const unsigned winu = __reduce_min_sync(0xffffffffu, cand);
        if (winu == 0xFFFFFFFFu) break;
        const int win = (int)winu;

        if (lane < 4)
            out[PROP_OFF + it * 4 + lane] = g_sboxes[(size_t)win * 4 + lane];

        const unsigned* row = g_mask + (size_t)win * NWORDS;
#pragma unroll
        for (int t = 0; t < SCAN_WPL; t++) {
            const int w = lane + 32 * t;
            if (w < NWORDS && w >= (win >> 5)) {
                unsigned m = row[w];
                if (w == (win >> 5)) {
                    m |= (1u << (win & 31));
                    m &= ~((1u << (win & 31)) - 1u);
                }
                rem[t] |= m;
            }
        }
    }
    for (int idx = it * 4 + lane; idx < POST_NMS * 4; idx += 32)
        out[PROP_OFF + idx] = 0.f;
}

// ---------------- launcher ----------------
extern "C" void kernel_launch(void* const* d_in, const int* in_sizes, int n_in,
                              void* d_out, int out_size) {
    const float* feats   = (const float*)d_in[0];
    const float* ancs    = (const float*)d_in[1];
    const float* w_bneck = (const float*)d_in[3];
    const float* b_bneck = (const float*)d_in[4];
    const float* w_cls   = (const float*)d_in[5];
    const float* b_cls   = (const float*)d_in[6];
    const float* w_reg   = (const float*)d_in[7];
    const float* b_reg   = (const float*)d_in[8];
    float* out = (float*)d_out;

    cudaFuncSetAttribute(gemm_bneck_mma, cudaFuncAttributeMaxDynamicSharedMemorySize, GEMM_SMEM);
    cudaFuncSetAttribute(select_all, cudaFuncAttributeMaxDynamicSharedMemorySize, PRE_NMS * 8);
    cudaFuncSetAttribute(mask_kernel, cudaFuncAttributeMaxDynamicSharedMemorySize, PRE_NMS * 16);

    gemm_bneck_mma<<<dim3(8, 128), 128, GEMM_SMEM>>>(feats, w_bneck, b_bneck);
    head_kernel<<<M_ROWS / 64, 256>>>(ancs, w_cls, b_cls, w_reg, b_reg, out);
    select_all<<<SEL_BLOCKS, 256, PRE_NMS * 8>>>();
    mask_kernel<<<MASK_BLOCKS, MASK_THREADS, PRE_NMS * 16>>>();
    scan_kernel<<<1, 32>>>(out);
}